// round 7
// baseline (speedup 1.0000x reference)
#include <cuda_runtime.h>
#include <cstdint>
#include <cstring>
#include <vector>
#include <algorithm>

namespace {
constexpr int kN = 8192, kD = 512, kNC = 64, kNR = 5, kRC = kNC * kNR;
constexpr int kTK = 16, kIters = 20;
constexpr int kCH = 32, kCHP = kN / kCH;   // 32 chunks x 256 points

// ---------------- host-side JAX threefry2x32 ----------------
struct U2 { uint32_t a, b; };
static inline uint32_t rotl32(uint32_t v, int r) { return (v << r) | (v >> (32 - r)); }

static U2 threefry(U2 key, uint32_t x0, uint32_t x1) {
    uint32_t ks0 = key.a, ks1 = key.b, ks2 = key.a ^ key.b ^ 0x1BD11BDAu;
    const int ra[4] = {13, 15, 26, 6}, rb[4] = {17, 29, 16, 24};
    x0 += ks0; x1 += ks1;
    for (int i = 0; i < 4; i++) { x0 += x1; x1 = rotl32(x1, ra[i]); x1 ^= x0; }
    x0 += ks1; x1 += ks2 + 1u;
    for (int i = 0; i < 4; i++) { x0 += x1; x1 = rotl32(x1, rb[i]); x1 ^= x0; }
    x0 += ks2; x1 += ks0 + 2u;
    for (int i = 0; i < 4; i++) { x0 += x1; x1 = rotl32(x1, ra[i]); x1 ^= x0; }
    x0 += ks0; x1 += ks1 + 3u;
    for (int i = 0; i < 4; i++) { x0 += x1; x1 = rotl32(x1, rb[i]); x1 ^= x0; }
    x0 += ks1; x1 += ks2 + 4u;
    for (int i = 0; i < 4; i++) { x0 += x1; x1 = rotl32(x1, ra[i]); x1 ^= x0; }
    x0 += ks2; x1 += ks0 + 5u;
    return {x0, x1};
}

constexpr bool kPartitionable = true;

static void split_keys(U2 key, int n, U2* out) {
    if (kPartitionable) {
        for (int i = 0; i < n; i++) out[i] = threefry(key, 0u, (uint32_t)i);
    } else {
        std::vector<uint32_t> o(2 * n);
        for (int i = 0; i < n; i++) {
            U2 y = threefry(key, (uint32_t)i, (uint32_t)(n + i));
            o[i] = y.a; o[n + i] = y.b;
        }
        for (int j = 0; j < n; j++) out[j] = { o[2 * j], o[2 * j + 1] };
    }
}

static void random_bits32(U2 key, int n, uint32_t* bits) {
    if (kPartitionable) {
        for (int i = 0; i < n; i++) {
            U2 y = threefry(key, 0u, (uint32_t)i);
            bits[i] = y.a ^ y.b;
        }
    } else {
        int h = n / 2;
        for (int i = 0; i < h; i++) {
            U2 y = threefry(key, (uint32_t)i, (uint32_t)(h + i));
            bits[i] = y.a; bits[h + i] = y.b;
        }
    }
}

static void compute_init_indices(int out_idx[kRC]) {
    U2 master{0u, 1234u};
    U2 runkeys[kNR];
    split_keys(master, kNR, runkeys);
    std::vector<int> val(kN), tmp(kN);
    std::vector<uint64_t> kv(kN);
    std::vector<uint32_t> bits(kN);
    for (int r = 0; r < kNR; r++) {
        for (int i = 0; i < kN; i++) val[i] = i;
        U2 cur = runkeys[r];
        for (int round = 0; round < 2; round++) {
            U2 nk[2];
            split_keys(cur, 2, nk);
            cur = nk[0];
            random_bits32(nk[1], kN, bits.data());
            for (int i = 0; i < kN; i++)
                kv[i] = ((uint64_t)bits[i] << 32) | (uint32_t)i;
            std::sort(kv.begin(), kv.end());
            for (int i = 0; i < kN; i++) tmp[i] = val[(uint32_t)(kv[i] & 0xffffffffu)];
            val.swap(tmp);
        }
        for (int c = 0; c < kNC; c++) out_idx[r * kNC + c] = val[c];
    }
}
} // namespace

// ---------------- device scratch ----------------
__device__ float g_cent[kRC * kD];
__device__ float g_cnorm[kRC];
__device__ int   g_labels[kNR * kN];
__device__ int   g_knn[kN * kTK];
__device__ float g_part[(size_t)kNR * kCH * kNC * kD];
__device__ int   g_pcnt[kNR * kCH * kNC];

struct IdxArr { int v[kRC]; };

// ---------------- packed fp32x2 helpers (sm_103a FFMA2) ----------------
__device__ __forceinline__ uint64_t f2pack(float lo, float hi) {
    uint64_t r; asm("mov.b64 %0,{%1,%2};" : "=l"(r) : "f"(lo), "f"(hi)); return r;
}
__device__ __forceinline__ void f2unpack(uint64_t v, float& lo, float& hi) {
    asm("mov.b64 {%0,%1},%2;" : "=f"(lo), "=f"(hi) : "l"(v));
}
__device__ __forceinline__ uint64_t ffma2(uint64_t a, uint64_t b, uint64_t c) {
    uint64_t d; asm("fma.rn.f32x2 %0,%1,%2,%3;" : "=l"(d) : "l"(a), "l"(b), "l"(c)); return d;
}

// ---------------- kernel 1: sim GEMM (256x128 tile, 16x8/thread) ----------------
__global__ void __launch_bounds__(256) gemm_sim_kernel(
    const float* __restrict__ A, const float* __restrict__ B, float* __restrict__ C)
{
    __shared__ __align__(16) float As[16][260];
    __shared__ __align__(16) float Bs[16][132];
    const int n0 = blockIdx.x * 128, m0 = blockIdx.y * 256;
    const int tid = threadIdx.x;
    const int tx = tid & 15, ty = tid >> 4;
    const int lr = tid >> 2, lc = (tid & 3) << 2;

    uint64_t acc[8][8];
#pragma unroll
    for (int p = 0; p < 8; p++)
#pragma unroll
        for (int j = 0; j < 8; j++) acc[p][j] = 0ull;

    float4 ra[4], rb[2];
#pragma unroll
    for (int q = 0; q < 4; q++)
        ra[q] = *reinterpret_cast<const float4*>(&A[(size_t)(m0 + lr + q * 64) * kD + lc]);
#pragma unroll
    for (int q = 0; q < 2; q++)
        rb[q] = *reinterpret_cast<const float4*>(&B[(size_t)(n0 + lr + q * 64) * kD + lc]);

    for (int k0 = 0; k0 < kD; k0 += 16) {
#pragma unroll
        for (int q = 0; q < 4; q++) {
            As[lc + 0][lr + q * 64] = ra[q].x; As[lc + 1][lr + q * 64] = ra[q].y;
            As[lc + 2][lr + q * 64] = ra[q].z; As[lc + 3][lr + q * 64] = ra[q].w;
        }
#pragma unroll
        for (int q = 0; q < 2; q++) {
            Bs[lc + 0][lr + q * 64] = rb[q].x; Bs[lc + 1][lr + q * 64] = rb[q].y;
            Bs[lc + 2][lr + q * 64] = rb[q].z; Bs[lc + 3][lr + q * 64] = rb[q].w;
        }
        __syncthreads();
        if (k0 + 16 < kD) {
#pragma unroll
            for (int q = 0; q < 4; q++)
                ra[q] = *reinterpret_cast<const float4*>(&A[(size_t)(m0 + lr + q * 64) * kD + k0 + 16 + lc]);
#pragma unroll
            for (int q = 0; q < 2; q++)
                rb[q] = *reinterpret_cast<const float4*>(&B[(size_t)(n0 + lr + q * 64) * kD + k0 + 16 + lc]);
        }
#pragma unroll
        for (int k = 0; k < 16; k++) {
            uint64_t pa[8];
#pragma unroll
            for (int q = 0; q < 4; q++) {
                float4 a = *reinterpret_cast<const float4*>(&As[k][q * 64 + ty * 4]);
                pa[2 * q + 0] = reinterpret_cast<const uint64_t*>(&a)[0];
                pa[2 * q + 1] = reinterpret_cast<const uint64_t*>(&a)[1];
            }
            float4 b0 = *reinterpret_cast<const float4*>(&Bs[k][tx * 4]);
            float4 b1 = *reinterpret_cast<const float4*>(&Bs[k][64 + tx * 4]);
            float bv[8] = {b0.x, b0.y, b0.z, b0.w, b1.x, b1.y, b1.z, b1.w};
            uint64_t bb[8];
#pragma unroll
            for (int j = 0; j < 8; j++) bb[j] = f2pack(bv[j], bv[j]);
#pragma unroll
            for (int p = 0; p < 8; p++)
#pragma unroll
                for (int j = 0; j < 8; j++)
                    acc[p][j] = ffma2(pa[p], bb[j], acc[p][j]);
        }
        __syncthreads();
    }
#pragma unroll
    for (int p = 0; p < 8; p++) {
        int rbase = m0 + (p >> 1) * 64 + ty * 4 + (p & 1) * 2;
        float lo[8], hi[8];
#pragma unroll
        for (int j = 0; j < 8; j++) f2unpack(acc[p][j], lo[j], hi[j]);
#pragma unroll
        for (int h = 0; h < 2; h++) {
            int row = rbase + h;
            float* vals = h ? hi : lo;
#pragma unroll
            for (int jh = 0; jh < 2; jh++) {
                int col0 = n0 + jh * 64 + tx * 4;
                float4 v;
                v.x = vals[jh * 4 + 0]; v.y = vals[jh * 4 + 1];
                v.z = vals[jh * 4 + 2]; v.w = vals[jh * 4 + 3];
                if (row >= col0 && row < col0 + 4) (&v.x)[row - col0] += 10.f;
                *reinterpret_cast<float4*>(&C[(size_t)row * kN + col0]) = v;
            }
        }
    }
}

// ---------------- kernel 2: per-row top-16 ----------------
__device__ __forceinline__ bool beats(float v1, int i1, float v2, int i2) {
    return (v1 > v2) || (v1 == v2 && i1 < i2);
}

__global__ void __launch_bounds__(256) topk_kernel(const float* __restrict__ sim)
{
    __shared__ float sv[256 * 16];
    __shared__ int   si[256 * 16];
    const int row = blockIdx.x, t = threadIdx.x;
    float tv[16]; int ti[16];
#pragma unroll
    for (int k = 0; k < 16; k++) { tv[k] = -3.402823466e38f; ti[k] = 0x7fffffff; }

    const float* rp = sim + (size_t)row * kN;
    for (int j = t; j < kN; j += 256) {
        float v = rp[j];
        if (beats(v, j, tv[15], ti[15])) {
            float cv = v; int ci = j;
#pragma unroll
            for (int k = 0; k < 16; k++) {
                if (beats(cv, ci, tv[k], ti[k])) {
                    float fv = tv[k]; int fi = ti[k];
                    tv[k] = cv; ti[k] = ci; cv = fv; ci = fi;
                }
            }
        }
    }
#pragma unroll
    for (int k = 0; k < 16; k++) { sv[t * 16 + k] = tv[k]; si[t * 16 + k] = ti[k]; }
    __syncthreads();

    for (int s = 128; s >= 1; s >>= 1) {
        if (t < s) {
            float mv[16]; int mi[16];
            int ia = 0, ib = 0;
#pragma unroll
            for (int k = 0; k < 16; k++) {
                float av = sv[t * 16 + ia], bw = sv[(t + s) * 16 + ib];
                int   ai = si[t * 16 + ia], bj = si[(t + s) * 16 + ib];
                bool ta = beats(av, ai, bw, bj);
                mv[k] = ta ? av : bw; mi[k] = ta ? ai : bj;
                if (ta) ia++; else ib++;
            }
#pragma unroll
            for (int k = 0; k < 16; k++) { sv[t * 16 + k] = mv[k]; si[t * 16 + k] = mi[k]; }
        }
        __syncthreads();
    }
    if (t < kTK) g_knn[row * kTK + t] = si[t];
}

// ---------------- kernel 3: gather init centroids ----------------
__global__ void gather_kernel(const float* __restrict__ X, IdxArr ia)
{
    int b = blockIdx.x;
    int src = ia.v[b];
    for (int d = threadIdx.x; d < kD; d += blockDim.x)
        g_cent[(size_t)b * kD + d] = X[(size_t)src * kD + d];
}

// ---------------- kernel 4: centroid norms (initial) ----------------
__global__ void __launch_bounds__(128) cnorm_kernel()
{
    int rc = blockIdx.x;
    float s = 0.f;
    for (int d = threadIdx.x; d < kD; d += 128) {
        float v = g_cent[(size_t)rc * kD + d];
        s = fmaf(v, v, s);
    }
#pragma unroll
    for (int m = 16; m >= 1; m >>= 1) s += __shfl_xor_sync(0xffffffffu, s, m);
    __shared__ float red[4];
    if ((threadIdx.x & 31) == 0) red[threadIdx.x >> 5] = s;
    __syncthreads();
    if (threadIdx.x == 0) g_cnorm[rc] = red[0] + red[1] + red[2] + red[3];
}

// ---------------- kernel 5: fused dist-GEMM + argmin (2 runs/block) ----------------
__global__ void __launch_bounds__(256) assign_kernel(const float* __restrict__ X)
{
    __shared__ __align__(16) float As[16][260];
    __shared__ __align__(16) float Bs[16][132];
    __shared__ float cns[128];

    const int m0 = blockIdx.x * 256;
    const int ra_id = min(2 * (int)blockIdx.y, kNR - 1);
    const int rb_id = min(2 * (int)blockIdx.y + 1, kNR - 1);
    const float* BA = g_cent + (size_t)ra_id * kNC * kD;
    const float* BB = g_cent + (size_t)rb_id * kNC * kD;
    const int tid = threadIdx.x;
    const int tx = tid & 15, ty = tid >> 4;
    const int lr = tid >> 2, lc = (tid & 3) << 2;

    if (tid < 64) cns[tid] = g_cnorm[ra_id * kNC + tid];
    else if (tid < 128) cns[tid] = g_cnorm[rb_id * kNC + tid - 64];

    uint64_t acc[8][8];
#pragma unroll
    for (int p = 0; p < 8; p++)
#pragma unroll
        for (int j = 0; j < 8; j++) acc[p][j] = 0ull;

    float4 rra[4], rrb[2];
#pragma unroll
    for (int q = 0; q < 4; q++)
        rra[q] = *reinterpret_cast<const float4*>(&X[(size_t)(m0 + lr + q * 64) * kD + lc]);
    rrb[0] = *reinterpret_cast<const float4*>(&BA[(size_t)lr * kD + lc]);
    rrb[1] = *reinterpret_cast<const float4*>(&BB[(size_t)lr * kD + lc]);

    for (int k0 = 0; k0 < kD; k0 += 16) {
#pragma unroll
        for (int q = 0; q < 4; q++) {
            As[lc + 0][lr + q * 64] = rra[q].x; As[lc + 1][lr + q * 64] = rra[q].y;
            As[lc + 2][lr + q * 64] = rra[q].z; As[lc + 3][lr + q * 64] = rra[q].w;
        }
#pragma unroll
        for (int q = 0; q < 2; q++) {
            Bs[lc + 0][lr + q * 64] = rrb[q].x; Bs[lc + 1][lr + q * 64] = rrb[q].y;
            Bs[lc + 2][lr + q * 64] = rrb[q].z; Bs[lc + 3][lr + q * 64] = rrb[q].w;
        }
        __syncthreads();
        if (k0 + 16 < kD) {
#pragma unroll
            for (int q = 0; q < 4; q++)
                rra[q] = *reinterpret_cast<const float4*>(&X[(size_t)(m0 + lr + q * 64) * kD + k0 + 16 + lc]);
            rrb[0] = *reinterpret_cast<const float4*>(&BA[(size_t)lr * kD + k0 + 16 + lc]);
            rrb[1] = *reinterpret_cast<const float4*>(&BB[(size_t)lr * kD + k0 + 16 + lc]);
        }
#pragma unroll
        for (int k = 0; k < 16; k++) {
            uint64_t pa[8];
#pragma unroll
            for (int q = 0; q < 4; q++) {
                float4 a = *reinterpret_cast<const float4*>(&As[k][q * 64 + ty * 4]);
                pa[2 * q + 0] = reinterpret_cast<const uint64_t*>(&a)[0];
                pa[2 * q + 1] = reinterpret_cast<const uint64_t*>(&a)[1];
            }
            float4 b0 = *reinterpret_cast<const float4*>(&Bs[k][tx * 4]);
            float4 b1 = *reinterpret_cast<const float4*>(&Bs[k][64 + tx * 4]);
            float bv[8] = {b0.x, b0.y, b0.z, b0.w, b1.x, b1.y, b1.z, b1.w};
            uint64_t bb[8];
#pragma unroll
            for (int j = 0; j < 8; j++) bb[j] = f2pack(bv[j], bv[j]);
#pragma unroll
            for (int p = 0; p < 8; p++)
#pragma unroll
                for (int j = 0; j < 8; j++)
                    acc[p][j] = ffma2(pa[p], bb[j], acc[p][j]);
        }
        __syncthreads();
    }
#pragma unroll
    for (int p = 0; p < 8; p++) {
        int rbase = m0 + (p >> 1) * 64 + ty * 4 + (p & 1) * 2;
        float lo[8], hi[8];
#pragma unroll
        for (int j = 0; j < 8; j++) f2unpack(acc[p][j], lo[j], hi[j]);
#pragma unroll
        for (int h = 0; h < 2; h++) {
            int row = rbase + h;
            float* vals = h ? hi : lo;
#pragma unroll
            for (int half = 0; half < 2; half++) {   // half 0 = run A, 1 = run B
                int cbase = half * 64 + tx * 4;
                float bvm = cns[cbase] - 2.f * vals[half * 4];
                int   bi  = cbase;
#pragma unroll
                for (int j = 1; j < 4; j++) {
                    float v = cns[cbase + j] - 2.f * vals[half * 4 + j];
                    if (v < bvm) { bvm = v; bi = cbase + j; }
                }
#pragma unroll
                for (int m = 1; m < 16; m <<= 1) {
                    float ov = __shfl_xor_sync(0xffffffffu, bvm, m);
                    int   oi = __shfl_xor_sync(0xffffffffu, bi, m);
                    if (ov < bvm || (ov == bvm && oi < bi)) { bvm = ov; bi = oi; }
                }
                if (tx == 0) {
                    int rr = half ? rb_id : ra_id;
                    g_labels[rr * kN + row] = bi - half * 64;
                }
            }
        }
    }
}

// ---------------- kernel 6a: point-centric partial sums (d-split) ----------------
__global__ void __launch_bounds__(256) partial_kernel(const float* __restrict__ X)
{
    extern __shared__ float sm[];
    float* ssum = sm;                            // [kNC][256]
    int*   slab = (int*)(sm + kNC * 256);        // [kCHP]
    int*   scnt = (int*)(sm + kNC * 256) + kCHP; // [kNC]

    const int ch = blockIdx.x;
    const int r  = blockIdx.y >> 1, dh = blockIdx.y & 1;
    const int t = threadIdx.x;
    const int d = dh * 256 + t;
    const int p0 = ch * kCHP;
    const int* lab = g_labels + r * kN;

#pragma unroll
    for (int c = 0; c < kNC; c++) ssum[c * 256 + t] = 0.f;
    if (t < kNC) scnt[t] = 0;
    slab[t] = lab[p0 + t];
    __syncthreads();
    if (dh == 0) atomicAdd(&scnt[slab[t]], 1);
    __syncthreads();

    for (int i = 0; i < kCHP; i += 8) {
        float x0 = X[(size_t)(p0 + i + 0) * kD + d];
        float x1 = X[(size_t)(p0 + i + 1) * kD + d];
        float x2 = X[(size_t)(p0 + i + 2) * kD + d];
        float x3 = X[(size_t)(p0 + i + 3) * kD + d];
        float x4 = X[(size_t)(p0 + i + 4) * kD + d];
        float x5 = X[(size_t)(p0 + i + 5) * kD + d];
        float x6 = X[(size_t)(p0 + i + 6) * kD + d];
        float x7 = X[(size_t)(p0 + i + 7) * kD + d];
        int c0 = slab[i + 0], c1 = slab[i + 1], c2 = slab[i + 2], c3 = slab[i + 3];
        int c4 = slab[i + 4], c5 = slab[i + 5], c6 = slab[i + 6], c7 = slab[i + 7];
        ssum[c0 * 256 + t] += x0;
        ssum[c1 * 256 + t] += x1;
        ssum[c2 * 256 + t] += x2;
        ssum[c3 * 256 + t] += x3;
        ssum[c4 * 256 + t] += x4;
        ssum[c5 * 256 + t] += x5;
        ssum[c6 * 256 + t] += x6;
        ssum[c7 * 256 + t] += x7;
    }
    __syncthreads();

    const size_t base = (size_t)(r * kCH + ch) * kNC;
#pragma unroll
    for (int c = 0; c < kNC; c++)
        g_part[(base + c) * kD + d] = ssum[c * 256 + t];
    if (dh == 0 && t < kNC) g_pcnt[base + t] = scnt[t];
}

// ---------------- kernel 6b: combine partials -> centroid + norm ----------------
__global__ void __launch_bounds__(512) combine_kernel()
{
    __shared__ float fred[16];
    const int c = blockIdx.x, r = blockIdx.y;
    const int t = threadIdx.x;
    const unsigned lane = t & 31;

    int cnt = 0;
    float sum = 0.f;
#pragma unroll
    for (int ch = 0; ch < kCH; ch++) {
        size_t base = (size_t)(r * kCH + ch) * kNC + c;
        cnt += g_pcnt[base];
        sum += g_part[base * kD + t];
    }
    const int rc = r * kNC + c;
    float oldc = g_cent[(size_t)rc * kD + t];
    float newc = (cnt > 0) ? (sum / (float)cnt) : oldc;
    g_cent[(size_t)rc * kD + t] = newc;

    float sq = newc * newc;
#pragma unroll
    for (int m = 16; m >= 1; m >>= 1) sq += __shfl_xor_sync(0xffffffffu, sq, m);
    if (lane == 0) fred[t >> 5] = sq;
    __syncthreads();
    if (t == 0) {
        float s = 0.f;
        for (int w = 0; w < 16; w++) s += fred[w];
        g_cnorm[rc] = s;
    }
}

// ---------------- kernel 7: scatter final output ----------------
__global__ void __launch_bounds__(256) scatter_kernel(
    const float* __restrict__ adj, float* __restrict__ out)
{
    int e = blockIdx.x * blockDim.x + threadIdx.x;
    int i = e >> 4;
    int j = g_knn[e];
    float v = adj[(size_t)i * kN + j];
    bool m = false;
#pragma unroll
    for (int r = 0; r < kNR; r++)
        m |= (g_labels[r * kN + i] == g_labels[r * kN + j]);
    out[(size_t)i * kN + j] = v + (m ? 1.f : 0.f);
}

// ---------------- launcher: two-stream overlap ----------------
extern "C" void kernel_launch(void* const* d_in, const int* in_sizes, int n_in,
                              void* d_out, int out_size)
{
    (void)in_sizes; (void)n_in; (void)out_size;
    const float* adj     = (const float*)d_in[0];
    const float* student = (const float*)d_in[1];
    const float* teacher = (const float*)d_in[2];
    float* out = (float*)d_out;

    constexpr size_t kPartSmem = (size_t)kNC * 256 * 4 + kCHP * 4 + kNC * 4;
    static cudaStream_t s2 = nullptr;
    static cudaEvent_t ev_fork = nullptr, ev_join = nullptr;
    if (!s2) {
        cudaStreamCreateWithFlags(&s2, cudaStreamNonBlocking);
        cudaEventCreateWithFlags(&ev_fork, cudaEventDisableTiming);
        cudaEventCreateWithFlags(&ev_join, cudaEventDisableTiming);
        cudaFuncSetAttribute(partial_kernel,
                             cudaFuncAttributeMaxDynamicSharedMemorySize, (int)kPartSmem);
    }

    IdxArr ia;
    compute_init_indices(ia.v);

    // fork: kmeans chain (teacher only) on s2
    cudaEventRecord(ev_fork, 0);
    cudaStreamWaitEvent(s2, ev_fork, 0);

    gather_kernel<<<kRC, 128, 0, s2>>>(teacher, ia);
    cnorm_kernel<<<kRC, 128, 0, s2>>>();
    dim3 ga(kN / 256, (kNR + 1) / 2), gp(kCH, kNR * 2), gc(kNC, kNR);
    for (int it = 0; it < kIters; it++) {
        assign_kernel<<<ga, 256, 0, s2>>>(teacher);
        partial_kernel<<<gp, 256, kPartSmem, s2>>>(teacher);
        combine_kernel<<<gc, 512, 0, s2>>>();
    }
    assign_kernel<<<ga, 256, 0, s2>>>(teacher);
    cudaEventRecord(ev_join, s2);

    // main stream: sim GEMM -> topk -> zero out
    dim3 g1(kN / 128, kN / 256);
    gemm_sim_kernel<<<g1, 256>>>(student, teacher, out);
    topk_kernel<<<kN, 256>>>(out);
    cudaMemsetAsync(d_out, 0, (size_t)kN * kN * sizeof(float), 0);

    // join + scatter
    cudaStreamWaitEvent(0, ev_join, 0);
    scatter_kernel<<<kN * kTK / 256, 256>>>(adj, out);
}

// round 8
// speedup vs baseline: 1.1126x; 1.1126x over previous
#include <cuda_runtime.h>
#include <cstdint>
#include <cstring>
#include <vector>
#include <algorithm>

namespace {
constexpr int kN = 8192, kD = 512, kNC = 64, kNR = 5, kRC = kNC * kNR;
constexpr int kTK = 16, kIters = 20;
constexpr int kCH = 32, kCHP = kN / kCH;   // 32 chunks x 256 points

// ---------------- host-side JAX threefry2x32 ----------------
struct U2 { uint32_t a, b; };
static inline uint32_t rotl32(uint32_t v, int r) { return (v << r) | (v >> (32 - r)); }

static U2 threefry(U2 key, uint32_t x0, uint32_t x1) {
    uint32_t ks0 = key.a, ks1 = key.b, ks2 = key.a ^ key.b ^ 0x1BD11BDAu;
    const int ra[4] = {13, 15, 26, 6}, rb[4] = {17, 29, 16, 24};
    x0 += ks0; x1 += ks1;
    for (int i = 0; i < 4; i++) { x0 += x1; x1 = rotl32(x1, ra[i]); x1 ^= x0; }
    x0 += ks1; x1 += ks2 + 1u;
    for (int i = 0; i < 4; i++) { x0 += x1; x1 = rotl32(x1, rb[i]); x1 ^= x0; }
    x0 += ks2; x1 += ks0 + 2u;
    for (int i = 0; i < 4; i++) { x0 += x1; x1 = rotl32(x1, ra[i]); x1 ^= x0; }
    x0 += ks0; x1 += ks1 + 3u;
    for (int i = 0; i < 4; i++) { x0 += x1; x1 = rotl32(x1, rb[i]); x1 ^= x0; }
    x0 += ks1; x1 += ks2 + 4u;
    for (int i = 0; i < 4; i++) { x0 += x1; x1 = rotl32(x1, ra[i]); x1 ^= x0; }
    x0 += ks2; x1 += ks0 + 5u;
    return {x0, x1};
}

constexpr bool kPartitionable = true;

static void split_keys(U2 key, int n, U2* out) {
    if (kPartitionable) {
        for (int i = 0; i < n; i++) out[i] = threefry(key, 0u, (uint32_t)i);
    } else {
        std::vector<uint32_t> o(2 * n);
        for (int i = 0; i < n; i++) {
            U2 y = threefry(key, (uint32_t)i, (uint32_t)(n + i));
            o[i] = y.a; o[n + i] = y.b;
        }
        for (int j = 0; j < n; j++) out[j] = { o[2 * j], o[2 * j + 1] };
    }
}

static void random_bits32(U2 key, int n, uint32_t* bits) {
    if (kPartitionable) {
        for (int i = 0; i < n; i++) {
            U2 y = threefry(key, 0u, (uint32_t)i);
            bits[i] = y.a ^ y.b;
        }
    } else {
        int h = n / 2;
        for (int i = 0; i < h; i++) {
            U2 y = threefry(key, (uint32_t)i, (uint32_t)(h + i));
            bits[i] = y.a; bits[h + i] = y.b;
        }
    }
}

static void compute_init_indices(int out_idx[kRC]) {
    U2 master{0u, 1234u};
    U2 runkeys[kNR];
    split_keys(master, kNR, runkeys);
    std::vector<int> val(kN), tmp(kN);
    std::vector<uint64_t> kv(kN);
    std::vector<uint32_t> bits(kN);
    for (int r = 0; r < kNR; r++) {
        for (int i = 0; i < kN; i++) val[i] = i;
        U2 cur = runkeys[r];
        for (int round = 0; round < 2; round++) {
            U2 nk[2];
            split_keys(cur, 2, nk);
            cur = nk[0];
            random_bits32(nk[1], kN, bits.data());
            for (int i = 0; i < kN; i++)
                kv[i] = ((uint64_t)bits[i] << 32) | (uint32_t)i;
            std::sort(kv.begin(), kv.end());
            for (int i = 0; i < kN; i++) tmp[i] = val[(uint32_t)(kv[i] & 0xffffffffu)];
            val.swap(tmp);
        }
        for (int c = 0; c < kNC; c++) out_idx[r * kNC + c] = val[c];
    }
}
} // namespace

// ---------------- device scratch ----------------
__device__ float g_cent[kRC * kD];
__device__ float g_cnorm[kRC];
__device__ int   g_labels[kNR * kN];
__device__ int   g_knn[kN * kTK];
__device__ float g_part[(size_t)kNR * kCH * kNC * kD];
__device__ int   g_pcnt[kNR * kCH * kNC];

struct IdxArr { int v[kRC]; };

// ---------------- packed fp32x2 helpers (sm_103a FFMA2) ----------------
__device__ __forceinline__ uint64_t f2pack(float lo, float hi) {
    uint64_t r; asm("mov.b64 %0,{%1,%2};" : "=l"(r) : "f"(lo), "f"(hi)); return r;
}
__device__ __forceinline__ void f2unpack(uint64_t v, float& lo, float& hi) {
    asm("mov.b64 {%0,%1},%2;" : "=f"(lo), "=f"(hi) : "l"(v));
}
__device__ __forceinline__ uint64_t ffma2(uint64_t a, uint64_t b, uint64_t c) {
    uint64_t d; asm("fma.rn.f32x2 %0,%1,%2,%3;" : "=l"(d) : "l"(a), "l"(b), "l"(c)); return d;
}

// ---------------- kernel 1: sim GEMM (prefetch double-buffered, 128x128) ----------------
__global__ void __launch_bounds__(256) gemm_sim_kernel(
    const float* __restrict__ A, const float* __restrict__ B, float* __restrict__ C)
{
    __shared__ __align__(16) float As[16][132];
    __shared__ __align__(16) float Bs[16][132];
    const int m0 = blockIdx.y * 128, n0 = blockIdx.x * 128;
    const int tid = threadIdx.x;
    const int tx = tid & 15, ty = tid >> 4;
    const int lr = tid >> 2, lc = (tid & 3) << 2;

    uint64_t accp[4][8];
#pragma unroll
    for (int p = 0; p < 4; p++)
#pragma unroll
        for (int j = 0; j < 8; j++) accp[p][j] = 0ull;

    float4 ra[2], rb[2];
#pragma unroll
    for (int q = 0; q < 2; q++) {
        ra[q] = *reinterpret_cast<const float4*>(&A[(size_t)(m0 + lr + q * 64) * kD + lc]);
        rb[q] = *reinterpret_cast<const float4*>(&B[(size_t)(n0 + lr + q * 64) * kD + lc]);
    }

    for (int k0 = 0; k0 < kD; k0 += 16) {
#pragma unroll
        for (int q = 0; q < 2; q++) {
            As[lc + 0][lr + q * 64] = ra[q].x; As[lc + 1][lr + q * 64] = ra[q].y;
            As[lc + 2][lr + q * 64] = ra[q].z; As[lc + 3][lr + q * 64] = ra[q].w;
            Bs[lc + 0][lr + q * 64] = rb[q].x; Bs[lc + 1][lr + q * 64] = rb[q].y;
            Bs[lc + 2][lr + q * 64] = rb[q].z; Bs[lc + 3][lr + q * 64] = rb[q].w;
        }
        __syncthreads();
        if (k0 + 16 < kD) {
#pragma unroll
            for (int q = 0; q < 2; q++) {
                ra[q] = *reinterpret_cast<const float4*>(&A[(size_t)(m0 + lr + q * 64) * kD + k0 + 16 + lc]);
                rb[q] = *reinterpret_cast<const float4*>(&B[(size_t)(n0 + lr + q * 64) * kD + k0 + 16 + lc]);
            }
        }
#pragma unroll
        for (int k = 0; k < 16; k++) {
            float4 a0 = *reinterpret_cast<const float4*>(&As[k][ty * 4]);
            float4 a1 = *reinterpret_cast<const float4*>(&As[k][64 + ty * 4]);
            float4 b0 = *reinterpret_cast<const float4*>(&Bs[k][tx * 4]);
            float4 b1 = *reinterpret_cast<const float4*>(&Bs[k][64 + tx * 4]);
            uint64_t pa[4];
            pa[0] = reinterpret_cast<const uint64_t*>(&a0)[0];
            pa[1] = reinterpret_cast<const uint64_t*>(&a0)[1];
            pa[2] = reinterpret_cast<const uint64_t*>(&a1)[0];
            pa[3] = reinterpret_cast<const uint64_t*>(&a1)[1];
            float bv[8] = {b0.x, b0.y, b0.z, b0.w, b1.x, b1.y, b1.z, b1.w};
            uint64_t bb[8];
#pragma unroll
            for (int j = 0; j < 8; j++) bb[j] = f2pack(bv[j], bv[j]);
#pragma unroll
            for (int p = 0; p < 4; p++)
#pragma unroll
                for (int j = 0; j < 8; j++)
                    accp[p][j] = ffma2(pa[p], bb[j], accp[p][j]);
        }
        __syncthreads();
    }
#pragma unroll
    for (int p = 0; p < 4; p++) {
        int base = (p < 2) ? (ty * 4 + 2 * p) : (64 + ty * 4 + 2 * (p - 2));
        float lo[8], hi[8];
#pragma unroll
        for (int j = 0; j < 8; j++) f2unpack(accp[p][j], lo[j], hi[j]);
#pragma unroll
        for (int h = 0; h < 2; h++) {
            int row = m0 + base + h;
            float* vals = h ? hi : lo;
#pragma unroll
            for (int jh = 0; jh < 2; jh++) {
                int col0 = n0 + jh * 64 + tx * 4;
                float4 v;
                v.x = vals[jh * 4 + 0]; v.y = vals[jh * 4 + 1];
                v.z = vals[jh * 4 + 2]; v.w = vals[jh * 4 + 3];
                if (row >= col0 && row < col0 + 4) (&v.x)[row - col0] += 10.f;
                *reinterpret_cast<float4*>(&C[(size_t)row * kN + col0]) = v;
            }
        }
    }
}

// ---------------- kernel 2: per-row top-16 ----------------
__device__ __forceinline__ bool beats(float v1, int i1, float v2, int i2) {
    return (v1 > v2) || (v1 == v2 && i1 < i2);
}

__global__ void __launch_bounds__(256) topk_kernel(const float* __restrict__ sim)
{
    __shared__ float sv[256 * 16];
    __shared__ int   si[256 * 16];
    const int row = blockIdx.x, t = threadIdx.x;
    float tv[16]; int ti[16];
#pragma unroll
    for (int k = 0; k < 16; k++) { tv[k] = -3.402823466e38f; ti[k] = 0x7fffffff; }

    const float* rp = sim + (size_t)row * kN;
    for (int j = t; j < kN; j += 256) {
        float v = rp[j];
        if (beats(v, j, tv[15], ti[15])) {
            float cv = v; int ci = j;
#pragma unroll
            for (int k = 0; k < 16; k++) {
                if (beats(cv, ci, tv[k], ti[k])) {
                    float fv = tv[k]; int fi = ti[k];
                    tv[k] = cv; ti[k] = ci; cv = fv; ci = fi;
                }
            }
        }
    }
#pragma unroll
    for (int k = 0; k < 16; k++) { sv[t * 16 + k] = tv[k]; si[t * 16 + k] = ti[k]; }
    __syncthreads();

    for (int s = 128; s >= 1; s >>= 1) {
        if (t < s) {
            float mv[16]; int mi[16];
            int ia = 0, ib = 0;
#pragma unroll
            for (int k = 0; k < 16; k++) {
                float av = sv[t * 16 + ia], bw = sv[(t + s) * 16 + ib];
                int   ai = si[t * 16 + ia], bj = si[(t + s) * 16 + ib];
                bool ta = beats(av, ai, bw, bj);
                mv[k] = ta ? av : bw; mi[k] = ta ? ai : bj;
                if (ta) ia++; else ib++;
            }
#pragma unroll
            for (int k = 0; k < 16; k++) { sv[t * 16 + k] = mv[k]; si[t * 16 + k] = mi[k]; }
        }
        __syncthreads();
    }
    if (t < kTK) g_knn[row * kTK + t] = si[t];
}

// ---------------- kernel 3: gather init centroids ----------------
__global__ void gather_kernel(const float* __restrict__ X, IdxArr ia)
{
    int b = blockIdx.x;
    int src = ia.v[b];
    for (int d = threadIdx.x; d < kD; d += blockDim.x)
        g_cent[(size_t)b * kD + d] = X[(size_t)src * kD + d];
}

// ---------------- kernel 4: centroid norms (initial) ----------------
__global__ void __launch_bounds__(128) cnorm_kernel()
{
    int rc = blockIdx.x;
    float s = 0.f;
    for (int d = threadIdx.x; d < kD; d += 128) {
        float v = g_cent[(size_t)rc * kD + d];
        s = fmaf(v, v, s);
    }
#pragma unroll
    for (int m = 16; m >= 1; m >>= 1) s += __shfl_xor_sync(0xffffffffu, s, m);
    __shared__ float red[4];
    if ((threadIdx.x & 31) == 0) red[threadIdx.x >> 5] = s;
    __syncthreads();
    if (threadIdx.x == 0) g_cnorm[rc] = red[0] + red[1] + red[2] + red[3];
}

// ---------------- kernel 5: fused dist-GEMM + argmin (prefetch, 128x64) ----------------
__global__ void __launch_bounds__(256) assign_kernel(const float* __restrict__ X)
{
    __shared__ __align__(16) float As[16][132];
    __shared__ __align__(16) float Bs[16][68];
    __shared__ float cns[kNC];

    const int r = blockIdx.y, m0 = blockIdx.x * 128;
    const float* B = g_cent + (size_t)r * kNC * kD;
    const int tid = threadIdx.x;
    const int tx = tid & 15, ty = tid >> 4;
    const int lr = tid >> 2, lc = (tid & 3) << 2;

    if (tid < kNC) cns[tid] = g_cnorm[r * kNC + tid];

    uint64_t accp[4][4];
#pragma unroll
    for (int p = 0; p < 4; p++)
#pragma unroll
        for (int j = 0; j < 4; j++) accp[p][j] = 0ull;

    float4 ra[2], rb;
#pragma unroll
    for (int q = 0; q < 2; q++)
        ra[q] = *reinterpret_cast<const float4*>(&X[(size_t)(m0 + lr + q * 64) * kD + lc]);
    rb = *reinterpret_cast<const float4*>(&B[(size_t)lr * kD + lc]);

    for (int k0 = 0; k0 < kD; k0 += 16) {
#pragma unroll
        for (int q = 0; q < 2; q++) {
            As[lc + 0][lr + q * 64] = ra[q].x; As[lc + 1][lr + q * 64] = ra[q].y;
            As[lc + 2][lr + q * 64] = ra[q].z; As[lc + 3][lr + q * 64] = ra[q].w;
        }
        Bs[lc + 0][lr] = rb.x; Bs[lc + 1][lr] = rb.y;
        Bs[lc + 2][lr] = rb.z; Bs[lc + 3][lr] = rb.w;
        __syncthreads();
        if (k0 + 16 < kD) {
#pragma unroll
            for (int q = 0; q < 2; q++)
                ra[q] = *reinterpret_cast<const float4*>(&X[(size_t)(m0 + lr + q * 64) * kD + k0 + 16 + lc]);
            rb = *reinterpret_cast<const float4*>(&B[(size_t)lr * kD + k0 + 16 + lc]);
        }
#pragma unroll
        for (int k = 0; k < 16; k++) {
            float4 a0 = *reinterpret_cast<const float4*>(&As[k][ty * 4]);
            float4 a1 = *reinterpret_cast<const float4*>(&As[k][64 + ty * 4]);
            float4 b  = *reinterpret_cast<const float4*>(&Bs[k][tx * 4]);
            uint64_t pa[4];
            pa[0] = reinterpret_cast<const uint64_t*>(&a0)[0];
            pa[1] = reinterpret_cast<const uint64_t*>(&a0)[1];
            pa[2] = reinterpret_cast<const uint64_t*>(&a1)[0];
            pa[3] = reinterpret_cast<const uint64_t*>(&a1)[1];
            float bv[4] = {b.x, b.y, b.z, b.w};
            uint64_t bb[4];
#pragma unroll
            for (int j = 0; j < 4; j++) bb[j] = f2pack(bv[j], bv[j]);
#pragma unroll
            for (int p = 0; p < 4; p++)
#pragma unroll
                for (int j = 0; j < 4; j++)
                    accp[p][j] = ffma2(pa[p], bb[j], accp[p][j]);
        }
        __syncthreads();
    }
#pragma unroll
    for (int p = 0; p < 4; p++) {
        int base = (p < 2) ? (ty * 4 + 2 * p) : (64 + ty * 4 + 2 * (p - 2));
        float lo[4], hi[4];
#pragma unroll
        for (int j = 0; j < 4; j++) f2unpack(accp[p][j], lo[j], hi[j]);
#pragma unroll
        for (int h = 0; h < 2; h++) {
            float* vals = h ? hi : lo;
            float bvm = cns[tx * 4] - 2.f * vals[0];
            int   bi  = tx * 4;
#pragma unroll
            for (int j = 1; j < 4; j++) {
                float v = cns[tx * 4 + j] - 2.f * vals[j];
                if (v < bvm) { bvm = v; bi = tx * 4 + j; }
            }
#pragma unroll
            for (int m = 1; m < 16; m <<= 1) {
                float ov = __shfl_xor_sync(0xffffffffu, bvm, m);
                int   oi = __shfl_xor_sync(0xffffffffu, bi, m);
                if (ov < bvm || (ov == bvm && oi < bi)) { bvm = ov; bi = oi; }
            }
            if (tx == 0) g_labels[r * kN + m0 + base + h] = bi;
        }
    }
}

// ---------------- kernel 6a: point-centric partial sums (d-split) ----------------
__global__ void __launch_bounds__(256) partial_kernel(const float* __restrict__ X)
{
    extern __shared__ float sm[];
    float* ssum = sm;                            // [kNC][256]
    int*   slab = (int*)(sm + kNC * 256);        // [kCHP]
    int*   scnt = (int*)(sm + kNC * 256) + kCHP; // [kNC]

    const int ch = blockIdx.x;
    const int r  = blockIdx.y >> 1, dh = blockIdx.y & 1;
    const int t = threadIdx.x;
    const int d = dh * 256 + t;
    const int p0 = ch * kCHP;
    const int* lab = g_labels + r * kN;

#pragma unroll
    for (int c = 0; c < kNC; c++) ssum[c * 256 + t] = 0.f;
    if (t < kNC) scnt[t] = 0;
    slab[t] = lab[p0 + t];
    __syncthreads();
    if (dh == 0) atomicAdd(&scnt[slab[t]], 1);
    __syncthreads();

    for (int i = 0; i < kCHP; i += 8) {
        float x0 = X[(size_t)(p0 + i + 0) * kD + d];
        float x1 = X[(size_t)(p0 + i + 1) * kD + d];
        float x2 = X[(size_t)(p0 + i + 2) * kD + d];
        float x3 = X[(size_t)(p0 + i + 3) * kD + d];
        float x4 = X[(size_t)(p0 + i + 4) * kD + d];
        float x5 = X[(size_t)(p0 + i + 5) * kD + d];
        float x6 = X[(size_t)(p0 + i + 6) * kD + d];
        float x7 = X[(size_t)(p0 + i + 7) * kD + d];
        int c0 = slab[i + 0], c1 = slab[i + 1], c2 = slab[i + 2], c3 = slab[i + 3];
        int c4 = slab[i + 4], c5 = slab[i + 5], c6 = slab[i + 6], c7 = slab[i + 7];
        ssum[c0 * 256 + t] += x0;
        ssum[c1 * 256 + t] += x1;
        ssum[c2 * 256 + t] += x2;
        ssum[c3 * 256 + t] += x3;
        ssum[c4 * 256 + t] += x4;
        ssum[c5 * 256 + t] += x5;
        ssum[c6 * 256 + t] += x6;
        ssum[c7 * 256 + t] += x7;
    }
    __syncthreads();

    const size_t base = (size_t)(r * kCH + ch) * kNC;
#pragma unroll
    for (int c = 0; c < kNC; c++)
        g_part[(base + c) * kD + d] = ssum[c * 256 + t];
    if (dh == 0 && t < kNC) g_pcnt[base + t] = scnt[t];
}

// ---------------- kernel 6b: combine partials -> centroid + norm ----------------
__global__ void __launch_bounds__(512) combine_kernel()
{
    __shared__ float fred[16];
    const int c = blockIdx.x, r = blockIdx.y;
    const int t = threadIdx.x;
    const unsigned lane = t & 31;

    int cnt = 0;
    float sum = 0.f;
#pragma unroll
    for (int ch = 0; ch < kCH; ch++) {
        size_t base = (size_t)(r * kCH + ch) * kNC + c;
        cnt += g_pcnt[base];
        sum += g_part[base * kD + t];
    }
    const int rc = r * kNC + c;
    float oldc = g_cent[(size_t)rc * kD + t];
    float newc = (cnt > 0) ? (sum / (float)cnt) : oldc;
    g_cent[(size_t)rc * kD + t] = newc;

    float sq = newc * newc;
#pragma unroll
    for (int m = 16; m >= 1; m >>= 1) sq += __shfl_xor_sync(0xffffffffu, sq, m);
    if (lane == 0) fred[t >> 5] = sq;
    __syncthreads();
    if (t == 0) {
        float s = 0.f;
        for (int w = 0; w < 16; w++) s += fred[w];
        g_cnorm[rc] = s;
    }
}

// ---------------- kernel 7: scatter final output ----------------
__global__ void __launch_bounds__(256) scatter_kernel(
    const float* __restrict__ adj, float* __restrict__ out)
{
    int e = blockIdx.x * blockDim.x + threadIdx.x;
    int i = e >> 4;
    int j = g_knn[e];
    float v = adj[(size_t)i * kN + j];
    bool m = false;
#pragma unroll
    for (int r = 0; r < kNR; r++)
        m |= (g_labels[r * kN + i] == g_labels[r * kN + j]);
    out[(size_t)i * kN + j] = v + (m ? 1.f : 0.f);
}

// ---------------- launcher: prioritized two-stream overlap ----------------
extern "C" void kernel_launch(void* const* d_in, const int* in_sizes, int n_in,
                              void* d_out, int out_size)
{
    (void)in_sizes; (void)n_in; (void)out_size;
    const float* adj     = (const float*)d_in[0];
    const float* student = (const float*)d_in[1];
    const float* teacher = (const float*)d_in[2];
    float* out = (float*)d_out;

    constexpr size_t kPartSmem = (size_t)kNC * 256 * 4 + kCHP * 4 + kNC * 4;
    static cudaStream_t s2 = nullptr, s1 = nullptr;
    static cudaEvent_t ev_fork = nullptr, ev_join = nullptr, ev_main = nullptr;
    if (!s2) {
        int lo, hi;
        cudaDeviceGetStreamPriorityRange(&lo, &hi);   // hi = greatest priority
        cudaStreamCreateWithPriority(&s2, cudaStreamNonBlocking, hi);  // kmeans: high
        cudaStreamCreateWithPriority(&s1, cudaStreamNonBlocking, lo);  // gemm: low
        cudaEventCreateWithFlags(&ev_fork, cudaEventDisableTiming);
        cudaEventCreateWithFlags(&ev_join, cudaEventDisableTiming);
        cudaEventCreateWithFlags(&ev_main, cudaEventDisableTiming);
        cudaFuncSetAttribute(partial_kernel,
                             cudaFuncAttributeMaxDynamicSharedMemorySize, (int)kPartSmem);
    }

    IdxArr ia;
    compute_init_indices(ia.v);

    // fork both worker streams from the capture (legacy) stream
    cudaEventRecord(ev_fork, 0);
    cudaStreamWaitEvent(s2, ev_fork, 0);
    cudaStreamWaitEvent(s1, ev_fork, 0);

    // s2 (HIGH priority): serial kmeans chain — latency-critical
    gather_kernel<<<kRC, 128, 0, s2>>>(teacher, ia);
    cnorm_kernel<<<kRC, 128, 0, s2>>>();
    dim3 ga(kN / 128, kNR), gp(kCH, kNR * 2), gc(kNC, kNR);
    for (int it = 0; it < kIters; it++) {
        assign_kernel<<<ga, 256, 0, s2>>>(teacher);
        partial_kernel<<<gp, 256, kPartSmem, s2>>>(teacher);
        combine_kernel<<<gc, 512, 0, s2>>>();
    }
    assign_kernel<<<ga, 256, 0, s2>>>(teacher);
    cudaEventRecord(ev_join, s2);

    // s1 (LOW priority): elastic throughput work — sim GEMM -> topk -> zero
    dim3 g1(kN / 128, kN / 128);
    gemm_sim_kernel<<<g1, 256, 0, s1>>>(student, teacher, out);
    topk_kernel<<<kN, 256, 0, s1>>>(out);
    cudaMemsetAsync(d_out, 0, (size_t)kN * kN * sizeof(float), s1);
    cudaEventRecord(ev_main, s1);

    // join on legacy stream + scatter
    cudaStreamWaitEvent(0, ev_join, 0);
    cudaStreamWaitEvent(0, ev_main, 0);
    scatter_kernel<<<kN * kTK / 256, 256>>>(adj, out);
}

// round 10
// speedup vs baseline: 1.1165x; 1.0035x over previous
#include <cuda_runtime.h>
#include <cstdint>
#include <cstring>
#include <vector>
#include <algorithm>

namespace {
constexpr int kN = 8192, kD = 512, kNC = 64, kNR = 5, kRC = kNC * kNR;
constexpr int kTK = 16, kIters = 20;
constexpr int kCH = 32, kCHP = kN / kCH;   // 32 chunks x 256 points

// ---------------- host-side JAX threefry2x32 ----------------
struct U2 { uint32_t a, b; };
static inline uint32_t rotl32(uint32_t v, int r) { return (v << r) | (v >> (32 - r)); }

static U2 threefry(U2 key, uint32_t x0, uint32_t x1) {
    uint32_t ks0 = key.a, ks1 = key.b, ks2 = key.a ^ key.b ^ 0x1BD11BDAu;
    const int ra[4] = {13, 15, 26, 6}, rb[4] = {17, 29, 16, 24};
    x0 += ks0; x1 += ks1;
    for (int i = 0; i < 4; i++) { x0 += x1; x1 = rotl32(x1, ra[i]); x1 ^= x0; }
    x0 += ks1; x1 += ks2 + 1u;
    for (int i = 0; i < 4; i++) { x0 += x1; x1 = rotl32(x1, rb[i]); x1 ^= x0; }
    x0 += ks2; x1 += ks0 + 2u;
    for (int i = 0; i < 4; i++) { x0 += x1; x1 = rotl32(x1, ra[i]); x1 ^= x0; }
    x0 += ks0; x1 += ks1 + 3u;
    for (int i = 0; i < 4; i++) { x0 += x1; x1 = rotl32(x1, rb[i]); x1 ^= x0; }
    x0 += ks1; x1 += ks2 + 4u;
    for (int i = 0; i < 4; i++) { x0 += x1; x1 = rotl32(x1, ra[i]); x1 ^= x0; }
    x0 += ks2; x1 += ks0 + 5u;
    return {x0, x1};
}

constexpr bool kPartitionable = true;

static void split_keys(U2 key, int n, U2* out) {
    if (kPartitionable) {
        for (int i = 0; i < n; i++) out[i] = threefry(key, 0u, (uint32_t)i);
    } else {
        std::vector<uint32_t> o(2 * n);
        for (int i = 0; i < n; i++) {
            U2 y = threefry(key, (uint32_t)i, (uint32_t)(n + i));
            o[i] = y.a; o[n + i] = y.b;
        }
        for (int j = 0; j < n; j++) out[j] = { o[2 * j], o[2 * j + 1] };
    }
}

static void random_bits32(U2 key, int n, uint32_t* bits) {
    if (kPartitionable) {
        for (int i = 0; i < n; i++) {
            U2 y = threefry(key, 0u, (uint32_t)i);
            bits[i] = y.a ^ y.b;
        }
    } else {
        int h = n / 2;
        for (int i = 0; i < h; i++) {
            U2 y = threefry(key, (uint32_t)i, (uint32_t)(h + i));
            bits[i] = y.a; bits[h + i] = y.b;
        }
    }
}

static void compute_init_indices(int out_idx[kRC]) {
    U2 master{0u, 1234u};
    U2 runkeys[kNR];
    split_keys(master, kNR, runkeys);
    std::vector<int> val(kN), tmp(kN);
    std::vector<uint64_t> kv(kN);
    std::vector<uint32_t> bits(kN);
    for (int r = 0; r < kNR; r++) {
        for (int i = 0; i < kN; i++) val[i] = i;
        U2 cur = runkeys[r];
        for (int round = 0; round < 2; round++) {
            U2 nk[2];
            split_keys(cur, 2, nk);
            cur = nk[0];
            random_bits32(nk[1], kN, bits.data());
            for (int i = 0; i < kN; i++)
                kv[i] = ((uint64_t)bits[i] << 32) | (uint32_t)i;
            std::sort(kv.begin(), kv.end());
            for (int i = 0; i < kN; i++) tmp[i] = val[(uint32_t)(kv[i] & 0xffffffffu)];
            val.swap(tmp);
        }
        for (int c = 0; c < kNC; c++) out_idx[r * kNC + c] = val[c];
    }
}
} // namespace

// ---------------- device scratch ----------------
__device__ float g_cent[kRC * kD];
__device__ float g_cnorm[kRC];
__device__ int   g_labels[kNR * kN];
__device__ int   g_knn[kN * kTK];
__device__ float g_part[(size_t)kNR * kCH * kNC * kD];
__device__ int   g_pcnt[kNR * kCH * kNC];
__device__ float g_Ahi[(size_t)kN * kD];
__device__ float g_Alo[(size_t)kN * kD];
__device__ float g_Bhi[(size_t)kN * kD];
__device__ float g_Blo[(size_t)kN * kD];

struct IdxArr { int v[kRC]; };

// ---------------- packed fp32x2 helpers (sm_103a FFMA2) ----------------
__device__ __forceinline__ uint64_t f2pack(float lo, float hi) {
    uint64_t r; asm("mov.b64 %0,{%1,%2};" : "=l"(r) : "f"(lo), "f"(hi)); return r;
}
__device__ __forceinline__ void f2unpack(uint64_t v, float& lo, float& hi) {
    asm("mov.b64 {%0,%1},%2;" : "=f"(lo), "=f"(hi) : "l"(v));
}
__device__ __forceinline__ uint64_t ffma2(uint64_t a, uint64_t b, uint64_t c) {
    uint64_t d; asm("fma.rn.f32x2 %0,%1,%2,%3;" : "=l"(d) : "l"(a), "l"(b), "l"(c)); return d;
}

// ---------------- tf32 helpers (Ampere-class mma.sync) ----------------
__device__ __forceinline__ float tf32r(float x) {
    uint32_t u; asm("cvt.rna.tf32.f32 %0,%1;" : "=r"(u) : "f"(x));
    return __uint_as_float(u);
}

#define MMA_TF32(d, a, b0, b1) \
    asm volatile( \
        "mma.sync.aligned.m16n8k8.row.col.f32.tf32.tf32.f32 " \
        "{%0,%1,%2,%3}, {%4,%5,%6,%7}, {%8,%9}, {%0,%1,%2,%3};" \
        : "+f"((d)[0]), "+f"((d)[1]), "+f"((d)[2]), "+f"((d)[3]) \
        : "r"((a)[0]), "r"((a)[1]), "r"((a)[2]), "r"((a)[3]), \
          "r"(b0), "r"(b1))

#define CP_ASYNC16(dst, src) \
    asm volatile("cp.async.cg.shared.global [%0], [%1], 16;" :: "r"(dst), "l"(src) : "memory")
#define CP_COMMIT() asm volatile("cp.async.commit_group;" ::: "memory")
#define CP_WAIT1()  asm volatile("cp.async.wait_group 1;" ::: "memory")
#define CP_WAIT0()  asm volatile("cp.async.wait_group 0;" ::: "memory")

// ---------------- kernel 0: fp32 -> tf32 hi/lo split ----------------
__device__ __forceinline__ void split1(float x, float& h, float& l) {
    h = tf32r(x);
    l = tf32r(x - h);
}

__global__ void __launch_bounds__(256) split_kernel(const float* __restrict__ A,
                                                    const float* __restrict__ B)
{
    size_t i = ((size_t)blockIdx.x * 256 + threadIdx.x) * 4;
    float4 a = *reinterpret_cast<const float4*>(A + i);
    float4 b = *reinterpret_cast<const float4*>(B + i);
    float4 ah, al, bh, bl;
    split1(a.x, ah.x, al.x); split1(a.y, ah.y, al.y);
    split1(a.z, ah.z, al.z); split1(a.w, ah.w, al.w);
    split1(b.x, bh.x, bl.x); split1(b.y, bh.y, bl.y);
    split1(b.z, bh.z, bl.z); split1(b.w, bh.w, bl.w);
    *reinterpret_cast<float4*>(g_Ahi + i) = ah;
    *reinterpret_cast<float4*>(g_Alo + i) = al;
    *reinterpret_cast<float4*>(g_Bhi + i) = bh;
    *reinterpret_cast<float4*>(g_Blo + i) = bl;
}

// ---------------- kernel 1: sim GEMM via mma.sync 3xTF32 ----------------
// CTA 128x128, 8 warps (4m x 2n), warp tile 32x64, K chunks of 32 floats.
// smem tiles row-major [128][36] floats (pitch 36 => conflict-free frag LDS),
// 4 parts (Ahi,Alo,Bhi,Blo) x 2 buffers = 8 x 18432 B = 144 KB.
namespace {
constexpr int kPitch = 36;
constexpr int kTileB = 128 * kPitch * 4;   // 18432
constexpr int kChunks = kD / 32;           // 16
}

__global__ void __launch_bounds__(256) gemm_mma_kernel(float* __restrict__ C)
{
    extern __shared__ char smem[];
    const int tid = threadIdx.x;
    const int lane = tid & 31, wid = tid >> 5;
    const int wm = wid & 3, wn = wid >> 2;
    const int gm = lane >> 2, gk = lane & 3;
    const int n0 = blockIdx.x * 128, m0 = blockIdx.y * 128;
    const uint32_t sbase = (uint32_t)__cvta_generic_to_shared(smem);

    float acc[2][8][4];
#pragma unroll
    for (int mt = 0; mt < 2; mt++)
#pragma unroll
        for (int nt = 0; nt < 8; nt++)
#pragma unroll
            for (int q = 0; q < 4; q++) acc[mt][nt][q] = 0.f;

    // staging geometry: per tile, thread copies 4 float4 granules
    int srow[4], sf4[4];
#pragma unroll
    for (int q = 0; q < 4; q++) {
        int idx = q * 256 + tid;
        srow[q] = idx >> 3;
        sf4[q]  = idx & 7;
    }

    auto copy_chunk = [&](int c, int buf) {
        const int koff = c * 32;
        const uint32_t tb = sbase + (uint32_t)buf * 4 * kTileB;
#pragma unroll
        for (int q = 0; q < 4; q++) {
            const int row = srow[q], f4 = sf4[q];
            const uint32_t doff = (uint32_t)(row * kPitch + f4 * 4) * 4;
            const size_t gA = (size_t)(m0 + row) * kD + koff + f4 * 4;
            const size_t gB = (size_t)(n0 + row) * kD + koff + f4 * 4;
            CP_ASYNC16(tb + 0 * kTileB + doff, g_Ahi + gA);
            CP_ASYNC16(tb + 1 * kTileB + doff, g_Alo + gA);
            CP_ASYNC16(tb + 2 * kTileB + doff, g_Bhi + gB);
            CP_ASYNC16(tb + 3 * kTileB + doff, g_Blo + gB);
        }
        CP_COMMIT();
    };

    copy_chunk(0, 0);
    copy_chunk(1, 1);

    for (int c = 0; c < kChunks; c++) {
        if (c < kChunks - 1) { CP_WAIT1(); } else { CP_WAIT0(); }
        __syncthreads();
        const int buf = c & 1;
        const float* Ah = reinterpret_cast<const float*>(smem + (size_t)(buf * 4 + 0) * kTileB);
        const float* Al = reinterpret_cast<const float*>(smem + (size_t)(buf * 4 + 1) * kTileB);
        const float* Bh = reinterpret_cast<const float*>(smem + (size_t)(buf * 4 + 2) * kTileB);
        const float* Bl = reinterpret_cast<const float*>(smem + (size_t)(buf * 4 + 3) * kTileB);

#pragma unroll
        for (int kk = 0; kk < 4; kk++) {
            const int kb = kk * 8 + gk;
            uint32_t ah[2][4], al[2][4];
#pragma unroll
            for (int mt = 0; mt < 2; mt++) {
                const int r0 = wm * 32 + mt * 16 + gm;
                ah[mt][0] = __float_as_uint(Ah[r0 * kPitch + kb]);
                ah[mt][1] = __float_as_uint(Ah[(r0 + 8) * kPitch + kb]);
                ah[mt][2] = __float_as_uint(Ah[r0 * kPitch + kb + 4]);
                ah[mt][3] = __float_as_uint(Ah[(r0 + 8) * kPitch + kb + 4]);
                al[mt][0] = __float_as_uint(Al[r0 * kPitch + kb]);
                al[mt][1] = __float_as_uint(Al[(r0 + 8) * kPitch + kb]);
                al[mt][2] = __float_as_uint(Al[r0 * kPitch + kb + 4]);
                al[mt][3] = __float_as_uint(Al[(r0 + 8) * kPitch + kb + 4]);
            }
#pragma unroll
            for (int nt = 0; nt < 8; nt++) {
                const int rB = wn * 64 + nt * 8 + gm;
                uint32_t bh0 = __float_as_uint(Bh[rB * kPitch + kb]);
                uint32_t bh1 = __float_as_uint(Bh[rB * kPitch + kb + 4]);
                uint32_t bl0 = __float_as_uint(Bl[rB * kPitch + kb]);
                uint32_t bl1 = __float_as_uint(Bl[rB * kPitch + kb + 4]);
                MMA_TF32(acc[0][nt], ah[0], bh0, bh1);
                MMA_TF32(acc[1][nt], ah[1], bh0, bh1);
                MMA_TF32(acc[0][nt], ah[0], bl0, bl1);
                MMA_TF32(acc[1][nt], ah[1], bl0, bl1);
                MMA_TF32(acc[0][nt], al[0], bh0, bh1);
                MMA_TF32(acc[1][nt], al[1], bh0, bh1);
            }
        }
        __syncthreads();
        if (c + 2 < kChunks) copy_chunk(c + 2, (c + 2) & 1);
    }

    // epilogue: +10*eye, store float2 pairs
#pragma unroll
    for (int mt = 0; mt < 2; mt++) {
#pragma unroll
        for (int nt = 0; nt < 8; nt++) {
            const int r0 = m0 + wm * 32 + mt * 16 + gm;
            const int r1 = r0 + 8;
            const int col = n0 + wn * 64 + nt * 8 + 2 * gk;
            float2 v0, v1;
            v0.x = acc[mt][nt][0] + ((r0 == col) ? 10.f : 0.f);
            v0.y = acc[mt][nt][1] + ((r0 == col + 1) ? 10.f : 0.f);
            v1.x = acc[mt][nt][2] + ((r1 == col) ? 10.f : 0.f);
            v1.y = acc[mt][nt][3] + ((r1 == col + 1) ? 10.f : 0.f);
            *reinterpret_cast<float2*>(&C[(size_t)r0 * kN + col]) = v0;
            *reinterpret_cast<float2*>(&C[(size_t)r1 * kN + col]) = v1;
        }
    }
}

// ---------------- kernel 2: per-row top-16 ----------------
__device__ __forceinline__ bool beats(float v1, int i1, float v2, int i2) {
    return (v1 > v2) || (v1 == v2 && i1 < i2);
}

__global__ void __launch_bounds__(256) topk_kernel(const float* __restrict__ sim)
{
    __shared__ float sv[256 * 16];
    __shared__ int   si[256 * 16];
    const int row = blockIdx.x, t = threadIdx.x;
    float tv[16]; int ti[16];
#pragma unroll
    for (int k = 0; k < 16; k++) { tv[k] = -3.402823466e38f; ti[k] = 0x7fffffff; }

    const float* rp = sim + (size_t)row * kN;
    for (int j = t; j < kN; j += 256) {
        float v = rp[j];
        if (beats(v, j, tv[15], ti[15])) {
            float cv = v; int ci = j;
#pragma unroll
            for (int k = 0; k < 16; k++) {
                if (beats(cv, ci, tv[k], ti[k])) {
                    float fv = tv[k]; int fi = ti[k];
                    tv[k] = cv; ti[k] = ci; cv = fv; ci = fi;
                }
            }
        }
    }
#pragma unroll
    for (int k = 0; k < 16; k++) { sv[t * 16 + k] = tv[k]; si[t * 16 + k] = ti[k]; }
    __syncthreads();

    for (int s = 128; s >= 1; s >>= 1) {
        if (t < s) {
            float mv[16]; int mi[16];
            int ia = 0, ib = 0;
#pragma unroll
            for (int k = 0; k < 16; k++) {
                float av = sv[t * 16 + ia], bw = sv[(t + s) * 16 + ib];
                int   ai = si[t * 16 + ia], bj = si[(t + s) * 16 + ib];
                bool ta = beats(av, ai, bw, bj);
                mv[k] = ta ? av : bw; mi[k] = ta ? ai : bj;
                if (ta) ia++; else ib++;
            }
#pragma unroll
            for (int k = 0; k < 16; k++) { sv[t * 16 + k] = mv[k]; si[t * 16 + k] = mi[k]; }
        }
        __syncthreads();
    }
    if (t < kTK) g_knn[row * kTK + t] = si[t];
}

// ---------------- kernel 3: gather init centroids ----------------
__global__ void gather_kernel(const float* __restrict__ X, IdxArr ia)
{
    int b = blockIdx.x;
    int src = ia.v[b];
    for (int d = threadIdx.x; d < kD; d += blockDim.x)
        g_cent[(size_t)b * kD + d] = X[(size_t)src * kD + d];
}

// ---------------- kernel 4: centroid norms (initial) ----------------
__global__ void __launch_bounds__(128) cnorm_kernel()
{
    int rc = blockIdx.x;
    float s = 0.f;
    for (int d = threadIdx.x; d < kD; d += 128) {
        float v = g_cent[(size_t)rc * kD + d];
        s = fmaf(v, v, s);
    }
#pragma unroll
    for (int m = 16; m >= 1; m >>= 1) s += __shfl_xor_sync(0xffffffffu, s, m);
    __shared__ float red[4];
    if ((threadIdx.x & 31) == 0) red[threadIdx.x >> 5] = s;
    __syncthreads();
    if (threadIdx.x == 0) g_cnorm[rc] = red[0] + red[1] + red[2] + red[3];
}

// ---------------- kernel 5: fused dist-GEMM + argmin (FFMA2, unchanged) ----------------
__global__ void __launch_bounds__(256) assign_kernel(const float* __restrict__ X)
{
    __shared__ __align__(16) float As[16][132];
    __shared__ __align__(16) float Bs[16][68];
    __shared__ float cns[kNC];

    const int r = blockIdx.y, m0 = blockIdx.x * 128;
    const float* B = g_cent + (size_t)r * kNC * kD;
    const int tid = threadIdx.x;
    const int tx = tid & 15, ty = tid >> 4;
    const int lr = tid >> 2, lc = (tid & 3) << 2;

    if (tid < kNC) cns[tid] = g_cnorm[r * kNC + tid];

    uint64_t accp[4][4];
#pragma unroll
    for (int p = 0; p < 4; p++)
#pragma unroll
        for (int j = 0; j < 4; j++) accp[p][j] = 0ull;

    float4 ra[2], rb;
#pragma unroll
    for (int q = 0; q < 2; q++)
        ra[q] = *reinterpret_cast<const float4*>(&X[(size_t)(m0 + lr + q * 64) * kD + lc]);
    rb = *reinterpret_cast<const float4*>(&B[(size_t)lr * kD + lc]);

    for (int k0 = 0; k0 < kD; k0 += 16) {
#pragma unroll
        for (int q = 0; q < 2; q++) {
            As[lc + 0][lr + q * 64] = ra[q].x; As[lc + 1][lr + q * 64] = ra[q].y;
            As[lc + 2][lr + q * 64] = ra[q].z; As[lc + 3][lr + q * 64] = ra[q].w;
        }
        Bs[lc + 0][lr] = rb.x; Bs[lc + 1][lr] = rb.y;
        Bs[lc + 2][lr] = rb.z; Bs[lc + 3][lr] = rb.w;
        __syncthreads();
        if (k0 + 16 < kD) {
#pragma unroll
            for (int q = 0; q < 2; q++)
                ra[q] = *reinterpret_cast<const float4*>(&X[(size_t)(m0 + lr + q * 64) * kD + k0 + 16 + lc]);
            rb = *reinterpret_cast<const float4*>(&B[(size_t)lr * kD + k0 + 16 + lc]);
        }
#pragma unroll
        for (int k = 0; k < 16; k++) {
            float4 a0 = *reinterpret_cast<const float4*>(&As[k][ty * 4]);
            float4 a1 = *reinterpret_cast<const float4*>(&As[k][64 + ty * 4]);
            float4 b  = *reinterpret_cast<const float4*>(&Bs[k][tx * 4]);
            uint64_t pa[4];
            pa[0] = reinterpret_cast<const uint64_t*>(&a0)[0];
            pa[1] = reinterpret_cast<const uint64_t*>(&a0)[1];
            pa[2] = reinterpret_cast<const uint64_t*>(&a1)[0];
            pa[3] = reinterpret_cast<const uint64_t*>(&a1)[1];
            float bv[4] = {b.x, b.y, b.z, b.w};
            uint64_t bb[4];
#pragma unroll
            for (int j = 0; j < 4; j++) bb[j] = f2pack(bv[j], bv[j]);
#pragma unroll
            for (int p = 0; p < 4; p++)
#pragma unroll
                for (int j = 0; j < 4; j++)
                    accp[p][j] = ffma2(pa[p], bb[j], accp[p][j]);
        }
        __syncthreads();
    }
#pragma unroll
    for (int p = 0; p < 4; p++) {
        int base = (p < 2) ? (ty * 4 + 2 * p) : (64 + ty * 4 + 2 * (p - 2));
        float lo[4], hi[4];
#pragma unroll
        for (int j = 0; j < 4; j++) f2unpack(accp[p][j], lo[j], hi[j]);
#pragma unroll
        for (int h = 0; h < 2; h++) {
            float* vals = h ? hi : lo;
            float bvm = cns[tx * 4] - 2.f * vals[0];
            int   bi  = tx * 4;
#pragma unroll
            for (int j = 1; j < 4; j++) {
                float v = cns[tx * 4 + j] - 2.f * vals[j];
                if (v < bvm) { bvm = v; bi = tx * 4 + j; }
            }
#pragma unroll
            for (int m = 1; m < 16; m <<= 1) {
                float ov = __shfl_xor_sync(0xffffffffu, bvm, m);
                int   oi = __shfl_xor_sync(0xffffffffu, bi, m);
                if (ov < bvm || (ov == bvm && oi < bi)) { bvm = ov; bi = oi; }
            }
            if (tx == 0) g_labels[r * kN + m0 + base + h] = bi;
        }
    }
}

// ---------------- kernel 6a: point-centric partial sums (d-split) ----------------
__global__ void __launch_bounds__(256) partial_kernel(const float* __restrict__ X)
{
    extern __shared__ float sm[];
    float* ssum = sm;                            // [kNC][256]
    int*   slab = (int*)(sm + kNC * 256);        // [kCHP]
    int*   scnt = (int*)(sm + kNC * 256) + kCHP; // [kNC]

    const int ch = blockIdx.x;
    const int r  = blockIdx.y >> 1, dh = blockIdx.y & 1;
    const int t = threadIdx.x;
    const int d = dh * 256 + t;
    const int p0 = ch * kCHP;
    const int* lab = g_labels + r * kN;

#pragma unroll
    for (int c = 0; c < kNC; c++) ssum[c * 256 + t] = 0.f;
    if (t < kNC) scnt[t] = 0;
    slab[t] = lab[p0 + t];
    __syncthreads();
    if (dh == 0) atomicAdd(&scnt[slab[t]], 1);
    __syncthreads();

    for (int i = 0; i < kCHP; i += 8) {
        float x0 = X[(size_t)(p0 + i + 0) * kD + d];
        float x1 = X[(size_t)(p0 + i + 1) * kD + d];
        float x2 = X[(size_t)(p0 + i + 2) * kD + d];
        float x3 = X[(size_t)(p0 + i + 3) * kD + d];
        float x4 = X[(size_t)(p0 + i + 4) * kD + d];
        float x5 = X[(size_t)(p0 + i + 5) * kD + d];
        float x6 = X[(size_t)(p0 + i + 6) * kD + d];
        float x7 = X[(size_t)(p0 + i + 7) * kD + d];
        int c0 = slab[i + 0], c1 = slab[i + 1], c2 = slab[i + 2], c3 = slab[i + 3];
        int c4 = slab[i + 4], c5 = slab[i + 5], c6 = slab[i + 6], c7 = slab[i + 7];
        ssum[c0 * 256 + t] += x0;
        ssum[c1 * 256 + t] += x1;
        ssum[c2 * 256 + t] += x2;
        ssum[c3 * 256 + t] += x3;
        ssum[c4 * 256 + t] += x4;
        ssum[c5 * 256 + t] += x5;
        ssum[c6 * 256 + t] += x6;
        ssum[c7 * 256 + t] += x7;
    }
    __syncthreads();

    const size_t base = (size_t)(r * kCH + ch) * kNC;
#pragma unroll
    for (int c = 0; c < kNC; c++)
        g_part[(base + c) * kD + d] = ssum[c * 256 + t];
    if (dh == 0 && t < kNC) g_pcnt[base + t] = scnt[t];
}

// ---------------- kernel 6b: combine partials -> centroid + norm ----------------
__global__ void __launch_bounds__(512) combine_kernel()
{
    __shared__ float fred[16];
    const int c = blockIdx.x, r = blockIdx.y;
    const int t = threadIdx.x;
    const unsigned lane = t & 31;

    int cnt = 0;
    float sum = 0.f;
#pragma unroll
    for (int ch = 0; ch < kCH; ch++) {
        size_t base = (size_t)(r * kCH + ch) * kNC + c;
        cnt += g_pcnt[base];
        sum += g_part[base * kD + t];
    }
    const int rc = r * kNC + c;
    float oldc = g_cent[(size_t)rc * kD + t];
    float newc = (cnt > 0) ? (sum / (float)cnt) : oldc;
    g_cent[(size_t)rc * kD + t] = newc;

    float sq = newc * newc;
#pragma unroll
    for (int m = 16; m >= 1; m >>= 1) sq += __shfl_xor_sync(0xffffffffu, sq, m);
    if (lane == 0) fred[t >> 5] = sq;
    __syncthreads();
    if (t == 0) {
        float s = 0.f;
        for (int w = 0; w < 16; w++) s += fred[w];
        g_cnorm[rc] = s;
    }
}

// ---------------- kernel 7: scatter final output ----------------
__global__ void __launch_bounds__(256) scatter_kernel(
    const float* __restrict__ adj, float* __restrict__ out)
{
    int e = blockIdx.x * blockDim.x + threadIdx.x;
    int i = e >> 4;
    int j = g_knn[e];
    float v = adj[(size_t)i * kN + j];
    bool m = false;
#pragma unroll
    for (int r = 0; r < kNR; r++)
        m |= (g_labels[r * kN + i] == g_labels[r * kN + j]);
    out[(size_t)i * kN + j] = v + (m ? 1.f : 0.f);
}

// ---------------- launcher ----------------
extern "C" void kernel_launch(void* const* d_in, const int* in_sizes, int n_in,
                              void* d_out, int out_size)
{
    (void)in_sizes; (void)n_in; (void)out_size;
    const float* adj     = (const float*)d_in[0];
    const float* student = (const float*)d_in[1];
    const float* teacher = (const float*)d_in[2];
    float* out = (float*)d_out;

    constexpr size_t kPartSmem = (size_t)kNC * 256 * 4 + kCHP * 4 + kNC * 4;
    constexpr size_t kGemmSmem = 8 * (size_t)kTileB;   // 144 KB
    static cudaStream_t s2 = nullptr, s1 = nullptr;
    static cudaEvent_t ev_fork = nullptr, ev_join = nullptr, ev_main = nullptr;
    if (!s2) {
        int lo, hi;
        cudaDeviceGetStreamPriorityRange(&lo, &hi);
        cudaStreamCreateWithPriority(&s2, cudaStreamNonBlocking, hi);
        cudaStreamCreateWithPriority(&s1, cudaStreamNonBlocking, lo);
        cudaEventCreateWithFlags(&ev_fork, cudaEventDisableTiming);
        cudaEventCreateWithFlags(&ev_join, cudaEventDisableTiming);
        cudaEventCreateWithFlags(&ev_main, cudaEventDisableTiming);
        cudaFuncSetAttribute(partial_kernel,
                             cudaFuncAttributeMaxDynamicSharedMemorySize, (int)kPartSmem);
        cudaFuncSetAttribute(gemm_mma_kernel,
                             cudaFuncAttributeMaxDynamicSharedMemorySize, (int)kGemmSmem);
    }

    IdxArr ia;
    compute_init_indices(ia.v);

    cudaEventRecord(ev_fork, 0);
    cudaStreamWaitEvent(s2, ev_fork, 0);
    cudaStreamWaitEvent(s1, ev_fork, 0);

    // s2: serial kmeans chain (fp32 FFMA2 — bit-identical to prior rounds)
    gather_kernel<<<kRC, 128, 0, s2>>>(teacher, ia);
    cnorm_kernel<<<kRC, 128, 0, s2>>>();
    dim3 ga(kN / 128, kNR), gp(kCH, kNR * 2), gc(kNC, kNR);
    for (int it = 0; it < kIters; it++) {
        assign_kernel<<<ga, 256, 0, s2>>>(teacher);
        partial_kernel<<<gp, 256, kPartSmem, s2>>>(teacher);
        combine_kernel<<<gc, 512, 0, s2>>>();
    }
    assign_kernel<<<ga, 256, 0, s2>>>(teacher);
    cudaEventRecord(ev_join, s2);

    // s1: tf32 split -> mma.sync sim GEMM -> topk -> zero out
    split_kernel<<<(kN * kD) / (256 * 4), 256, 0, s1>>>(student, teacher);
    dim3 g1(kN / 128, kN / 128);
    gemm_mma_kernel<<<g1, 256, kGemmSmem, s1>>>(out);
    topk_kernel<<<kN, 256, 0, s1>>>(out);
    cudaMemsetAsync(d_out, 0, (size_t)kN * kN * sizeof(float), s1);
    cudaEventRecord(ev_main, s1);

    cudaStreamWaitEvent(0, ev_join, 0);
    cudaStreamWaitEvent(0, ev_main, 0);
    scatter_kernel<<<kN * kTK / 256, 256>>>(adj, out);
}

// round 11
// speedup vs baseline: 1.1288x; 1.0110x over previous
#include <cuda_runtime.h>
#include <cstdint>
#include <cstring>
#include <vector>
#include <algorithm>

namespace {
constexpr int kN = 8192, kD = 512, kNC = 64, kNR = 5, kRC = kNC * kNR;
constexpr int kTK = 16, kIters = 20;
constexpr int kCH = 32, kCHP = kN / kCH;   // 32 chunks x 256 points

// ---------------- host-side JAX threefry2x32 ----------------
struct U2 { uint32_t a, b; };
static inline uint32_t rotl32(uint32_t v, int r) { return (v << r) | (v >> (32 - r)); }

static U2 threefry(U2 key, uint32_t x0, uint32_t x1) {
    uint32_t ks0 = key.a, ks1 = key.b, ks2 = key.a ^ key.b ^ 0x1BD11BDAu;
    const int ra[4] = {13, 15, 26, 6}, rb[4] = {17, 29, 16, 24};
    x0 += ks0; x1 += ks1;
    for (int i = 0; i < 4; i++) { x0 += x1; x1 = rotl32(x1, ra[i]); x1 ^= x0; }
    x0 += ks1; x1 += ks2 + 1u;
    for (int i = 0; i < 4; i++) { x0 += x1; x1 = rotl32(x1, rb[i]); x1 ^= x0; }
    x0 += ks2; x1 += ks0 + 2u;
    for (int i = 0; i < 4; i++) { x0 += x1; x1 = rotl32(x1, ra[i]); x1 ^= x0; }
    x0 += ks0; x1 += ks1 + 3u;
    for (int i = 0; i < 4; i++) { x0 += x1; x1 = rotl32(x1, rb[i]); x1 ^= x0; }
    x0 += ks1; x1 += ks2 + 4u;
    for (int i = 0; i < 4; i++) { x0 += x1; x1 = rotl32(x1, ra[i]); x1 ^= x0; }
    x0 += ks2; x1 += ks0 + 5u;
    return {x0, x1};
}

constexpr bool kPartitionable = true;

static void split_keys(U2 key, int n, U2* out) {
    if (kPartitionable) {
        for (int i = 0; i < n; i++) out[i] = threefry(key, 0u, (uint32_t)i);
    } else {
        std::vector<uint32_t> o(2 * n);
        for (int i = 0; i < n; i++) {
            U2 y = threefry(key, (uint32_t)i, (uint32_t)(n + i));
            o[i] = y.a; o[n + i] = y.b;
        }
        for (int j = 0; j < n; j++) out[j] = { o[2 * j], o[2 * j + 1] };
    }
}

static void random_bits32(U2 key, int n, uint32_t* bits) {
    if (kPartitionable) {
        for (int i = 0; i < n; i++) {
            U2 y = threefry(key, 0u, (uint32_t)i);
            bits[i] = y.a ^ y.b;
        }
    } else {
        int h = n / 2;
        for (int i = 0; i < h; i++) {
            U2 y = threefry(key, (uint32_t)i, (uint32_t)(h + i));
            bits[i] = y.a; bits[h + i] = y.b;
        }
    }
}

static void compute_init_indices(int out_idx[kRC]) {
    U2 master{0u, 1234u};
    U2 runkeys[kNR];
    split_keys(master, kNR, runkeys);
    std::vector<int> val(kN), tmp(kN);
    std::vector<uint64_t> kv(kN);
    std::vector<uint32_t> bits(kN);
    for (int r = 0; r < kNR; r++) {
        for (int i = 0; i < kN; i++) val[i] = i;
        U2 cur = runkeys[r];
        for (int round = 0; round < 2; round++) {
            U2 nk[2];
            split_keys(cur, 2, nk);
            cur = nk[0];
            random_bits32(nk[1], kN, bits.data());
            for (int i = 0; i < kN; i++)
                kv[i] = ((uint64_t)bits[i] << 32) | (uint32_t)i;
            std::sort(kv.begin(), kv.end());
            for (int i = 0; i < kN; i++) tmp[i] = val[(uint32_t)(kv[i] & 0xffffffffu)];
            val.swap(tmp);
        }
        for (int c = 0; c < kNC; c++) out_idx[r * kNC + c] = val[c];
    }
}
} // namespace

// ---------------- device scratch ----------------
__device__ float g_cent[kRC * kD];
__device__ float g_cnorm[kRC];
__device__ int   g_labels[kNR * kN];
__device__ int   g_knn[kN * kTK];
__device__ float g_part[(size_t)kNR * kCH * kNC * kD];
__device__ int   g_pcnt[kNR * kCH * kNC];
__device__ float g_Ahi[(size_t)kN * kD];   // student hi/lo
__device__ float g_Alo[(size_t)kN * kD];
__device__ float g_Bhi[(size_t)kN * kD];   // teacher hi/lo
__device__ float g_Blo[(size_t)kN * kD];
__device__ float g_Chi[(size_t)kRC * kD];  // centroid hi/lo
__device__ float g_Clo[(size_t)kRC * kD];

struct IdxArr { int v[kRC]; };

// ---------------- tf32 helpers (Ampere-class mma.sync) ----------------
__device__ __forceinline__ float tf32r(float x) {
    uint32_t u; asm("cvt.rna.tf32.f32 %0,%1;" : "=r"(u) : "f"(x));
    return __uint_as_float(u);
}

#define MMA_TF32(d, a, b0, b1) \
    asm volatile( \
        "mma.sync.aligned.m16n8k8.row.col.f32.tf32.tf32.f32 " \
        "{%0,%1,%2,%3}, {%4,%5,%6,%7}, {%8,%9}, {%0,%1,%2,%3};" \
        : "+f"((d)[0]), "+f"((d)[1]), "+f"((d)[2]), "+f"((d)[3]) \
        : "r"((a)[0]), "r"((a)[1]), "r"((a)[2]), "r"((a)[3]), \
          "r"(b0), "r"(b1))

#define CP_ASYNC16(dst, src) \
    asm volatile("cp.async.cg.shared.global [%0], [%1], 16;" :: "r"(dst), "l"(src) : "memory")
#define CP_COMMIT() asm volatile("cp.async.commit_group;" ::: "memory")
#define CP_WAIT1()  asm volatile("cp.async.wait_group 1;" ::: "memory")
#define CP_WAIT0()  asm volatile("cp.async.wait_group 0;" ::: "memory")

// ---------------- kernel 0: fp32 -> tf32 hi/lo split (inputs) ----------------
__device__ __forceinline__ void split1(float x, float& h, float& l) {
    h = tf32r(x);
    l = tf32r(x - h);
}

__global__ void __launch_bounds__(256) split_kernel(const float* __restrict__ A,
                                                    const float* __restrict__ B)
{
    size_t i = ((size_t)blockIdx.x * 256 + threadIdx.x) * 4;
    float4 a = *reinterpret_cast<const float4*>(A + i);
    float4 b = *reinterpret_cast<const float4*>(B + i);
    float4 ah, al, bh, bl;
    split1(a.x, ah.x, al.x); split1(a.y, ah.y, al.y);
    split1(a.z, ah.z, al.z); split1(a.w, ah.w, al.w);
    split1(b.x, bh.x, bl.x); split1(b.y, bh.y, bl.y);
    split1(b.z, bh.z, bl.z); split1(b.w, bh.w, bl.w);
    *reinterpret_cast<float4*>(g_Ahi + i) = ah;
    *reinterpret_cast<float4*>(g_Alo + i) = al;
    *reinterpret_cast<float4*>(g_Bhi + i) = bh;
    *reinterpret_cast<float4*>(g_Blo + i) = bl;
}

// ---------------- kernel 0b: centroid hi/lo split (per iteration) ----------------
__global__ void __launch_bounds__(256) split_cent_kernel()
{
    size_t i = ((size_t)blockIdx.x * 256 + threadIdx.x) * 4;
    float4 c = *reinterpret_cast<const float4*>(g_cent + i);
    float4 ch, cl;
    split1(c.x, ch.x, cl.x); split1(c.y, ch.y, cl.y);
    split1(c.z, ch.z, cl.z); split1(c.w, ch.w, cl.w);
    *reinterpret_cast<float4*>(g_Chi + i) = ch;
    *reinterpret_cast<float4*>(g_Clo + i) = cl;
}

// ---------------- kernel 1: sim GEMM via mma.sync 3xTF32 (unchanged R10) ------
namespace {
constexpr int kPitch = 36;
constexpr int kTileB = 128 * kPitch * 4;   // 18432
constexpr int kChunks = kD / 32;           // 16
}

__global__ void __launch_bounds__(256) gemm_mma_kernel(float* __restrict__ C)
{
    extern __shared__ char smem[];
    const int tid = threadIdx.x;
    const int lane = tid & 31, wid = tid >> 5;
    const int wm = wid & 3, wn = wid >> 2;
    const int gm = lane >> 2, gk = lane & 3;
    const int n0 = blockIdx.x * 128, m0 = blockIdx.y * 128;
    const uint32_t sbase = (uint32_t)__cvta_generic_to_shared(smem);

    float acc[2][8][4];
#pragma unroll
    for (int mt = 0; mt < 2; mt++)
#pragma unroll
        for (int nt = 0; nt < 8; nt++)
#pragma unroll
            for (int q = 0; q < 4; q++) acc[mt][nt][q] = 0.f;

    int srow[4], sf4[4];
#pragma unroll
    for (int q = 0; q < 4; q++) {
        int idx = q * 256 + tid;
        srow[q] = idx >> 3;
        sf4[q]  = idx & 7;
    }

    auto copy_chunk = [&](int c, int buf) {
        const int koff = c * 32;
        const uint32_t tb = sbase + (uint32_t)buf * 4 * kTileB;
#pragma unroll
        for (int q = 0; q < 4; q++) {
            const int row = srow[q], f4 = sf4[q];
            const uint32_t doff = (uint32_t)(row * kPitch + f4 * 4) * 4;
            const size_t gA = (size_t)(m0 + row) * kD + koff + f4 * 4;
            const size_t gB = (size_t)(n0 + row) * kD + koff + f4 * 4;
            CP_ASYNC16(tb + 0 * kTileB + doff, g_Ahi + gA);
            CP_ASYNC16(tb + 1 * kTileB + doff, g_Alo + gA);
            CP_ASYNC16(tb + 2 * kTileB + doff, g_Bhi + gB);
            CP_ASYNC16(tb + 3 * kTileB + doff, g_Blo + gB);
        }
        CP_COMMIT();
    };

    copy_chunk(0, 0);
    copy_chunk(1, 1);

    for (int c = 0; c < kChunks; c++) {
        if (c < kChunks - 1) { CP_WAIT1(); } else { CP_WAIT0(); }
        __syncthreads();
        const int buf = c & 1;
        const float* Ah = reinterpret_cast<const float*>(smem + (size_t)(buf * 4 + 0) * kTileB);
        const float* Al = reinterpret_cast<const float*>(smem + (size_t)(buf * 4 + 1) * kTileB);
        const float* Bh = reinterpret_cast<const float*>(smem + (size_t)(buf * 4 + 2) * kTileB);
        const float* Bl = reinterpret_cast<const float*>(smem + (size_t)(buf * 4 + 3) * kTileB);

#pragma unroll
        for (int kk = 0; kk < 4; kk++) {
            const int kb = kk * 8 + gk;
            uint32_t ah[2][4], al[2][4];
#pragma unroll
            for (int mt = 0; mt < 2; mt++) {
                const int r0 = wm * 32 + mt * 16 + gm;
                ah[mt][0] = __float_as_uint(Ah[r0 * kPitch + kb]);
                ah[mt][1] = __float_as_uint(Ah[(r0 + 8) * kPitch + kb]);
                ah[mt][2] = __float_as_uint(Ah[r0 * kPitch + kb + 4]);
                ah[mt][3] = __float_as_uint(Ah[(r0 + 8) * kPitch + kb + 4]);
                al[mt][0] = __float_as_uint(Al[r0 * kPitch + kb]);
                al[mt][1] = __float_as_uint(Al[(r0 + 8) * kPitch + kb]);
                al[mt][2] = __float_as_uint(Al[r0 * kPitch + kb + 4]);
                al[mt][3] = __float_as_uint(Al[(r0 + 8) * kPitch + kb + 4]);
            }
#pragma unroll
            for (int nt = 0; nt < 8; nt++) {
                const int rB = wn * 64 + nt * 8 + gm;
                uint32_t bh0 = __float_as_uint(Bh[rB * kPitch + kb]);
                uint32_t bh1 = __float_as_uint(Bh[rB * kPitch + kb + 4]);
                uint32_t bl0 = __float_as_uint(Bl[rB * kPitch + kb]);
                uint32_t bl1 = __float_as_uint(Bl[rB * kPitch + kb + 4]);
                MMA_TF32(acc[0][nt], ah[0], bh0, bh1);
                MMA_TF32(acc[1][nt], ah[1], bh0, bh1);
                MMA_TF32(acc[0][nt], ah[0], bl0, bl1);
                MMA_TF32(acc[1][nt], ah[1], bl0, bl1);
                MMA_TF32(acc[0][nt], al[0], bh0, bh1);
                MMA_TF32(acc[1][nt], al[1], bh0, bh1);
            }
        }
        __syncthreads();
        if (c + 2 < kChunks) copy_chunk(c + 2, (c + 2) & 1);
    }

#pragma unroll
    for (int mt = 0; mt < 2; mt++) {
#pragma unroll
        for (int nt = 0; nt < 8; nt++) {
            const int r0 = m0 + wm * 32 + mt * 16 + gm;
            const int r1 = r0 + 8;
            const int col = n0 + wn * 64 + nt * 8 + 2 * gk;
            float2 v0, v1;
            v0.x = acc[mt][nt][0] + ((r0 == col) ? 10.f : 0.f);
            v0.y = acc[mt][nt][1] + ((r0 == col + 1) ? 10.f : 0.f);
            v1.x = acc[mt][nt][2] + ((r1 == col) ? 10.f : 0.f);
            v1.y = acc[mt][nt][3] + ((r1 == col + 1) ? 10.f : 0.f);
            *reinterpret_cast<float2*>(&C[(size_t)r0 * kN + col]) = v0;
            *reinterpret_cast<float2*>(&C[(size_t)r1 * kN + col]) = v1;
        }
    }
}

// ---------------- kernel 2: per-row top-16 ----------------
__device__ __forceinline__ bool beats(float v1, int i1, float v2, int i2) {
    return (v1 > v2) || (v1 == v2 && i1 < i2);
}

__global__ void __launch_bounds__(256) topk_kernel(const float* __restrict__ sim)
{
    __shared__ float sv[256 * 16];
    __shared__ int   si[256 * 16];
    const int row = blockIdx.x, t = threadIdx.x;
    float tv[16]; int ti[16];
#pragma unroll
    for (int k = 0; k < 16; k++) { tv[k] = -3.402823466e38f; ti[k] = 0x7fffffff; }

    const float* rp = sim + (size_t)row * kN;
    for (int j = t; j < kN; j += 256) {
        float v = rp[j];
        if (beats(v, j, tv[15], ti[15])) {
            float cv = v; int ci = j;
#pragma unroll
            for (int k = 0; k < 16; k++) {
                if (beats(cv, ci, tv[k], ti[k])) {
                    float fv = tv[k]; int fi = ti[k];
                    tv[k] = cv; ti[k] = ci; cv = fv; ci = fi;
                }
            }
        }
    }
#pragma unroll
    for (int k = 0; k < 16; k++) { sv[t * 16 + k] = tv[k]; si[t * 16 + k] = ti[k]; }
    __syncthreads();

    for (int s = 128; s >= 1; s >>= 1) {
        if (t < s) {
            float mv[16]; int mi[16];
            int ia = 0, ib = 0;
#pragma unroll
            for (int k = 0; k < 16; k++) {
                float av = sv[t * 16 + ia], bw = sv[(t + s) * 16 + ib];
                int   ai = si[t * 16 + ia], bj = si[(t + s) * 16 + ib];
                bool ta = beats(av, ai, bw, bj);
                mv[k] = ta ? av : bw; mi[k] = ta ? ai : bj;
                if (ta) ia++; else ib++;
            }
#pragma unroll
            for (int k = 0; k < 16; k++) { sv[t * 16 + k] = mv[k]; si[t * 16 + k] = mi[k]; }
        }
        __syncthreads();
    }
    if (t < kTK) g_knn[row * kTK + t] = si[t];
}

// ---------------- kernel 3: gather init centroids ----------------
__global__ void gather_kernel(const float* __restrict__ X, IdxArr ia)
{
    int b = blockIdx.x;
    int src = ia.v[b];
    for (int d = threadIdx.x; d < kD; d += blockDim.x)
        g_cent[(size_t)b * kD + d] = X[(size_t)src * kD + d];
}

// ---------------- kernel 4: centroid norms (initial) ----------------
__global__ void __launch_bounds__(128) cnorm_kernel()
{
    int rc = blockIdx.x;
    float s = 0.f;
    for (int d = threadIdx.x; d < kD; d += 128) {
        float v = g_cent[(size_t)rc * kD + d];
        s = fmaf(v, v, s);
    }
#pragma unroll
    for (int m = 16; m >= 1; m >>= 1) s += __shfl_xor_sync(0xffffffffu, s, m);
    __shared__ float red[4];
    if ((threadIdx.x & 31) == 0) red[threadIdx.x >> 5] = s;
    __syncthreads();
    if (threadIdx.x == 0) g_cnorm[rc] = red[0] + red[1] + red[2] + red[3];
}

// ---------------- kernel 5: assign via mma.sync 3xTF32 + argmin ----------------
// CTA: 128 points x 64 centroids (one run). 8 warps: wm=wid&3 (32-row band),
// wn=wid>>2 (32-col half). Warp tile 32x32 = 2 mt x 4 nt m16n8k8 frags.
// smem/buf: Ah,Al 128x36f; Bh,Bl 64x36f  => buf 55296 B, x2 = 110592 B.
namespace {
constexpr int kATileB = 128 * kPitch * 4;   // 18432
constexpr int kBTileB = 64 * kPitch * 4;    // 9216
constexpr int kABufB  = 2 * kATileB + 2 * kBTileB;  // 55296
}

__device__ __forceinline__ bool better(float v, int i, float bv, int bi) {
    return (v < bv) || (v == bv && i < bi);
}

__global__ void __launch_bounds__(256) assign_mma_kernel()
{
    extern __shared__ char smem[];
    __shared__ float cns[kNC];
    __shared__ float sd[2][128];
    __shared__ int   sidx[2][128];

    const int tid = threadIdx.x;
    const int lane = tid & 31, wid = tid >> 5;
    const int wm = wid & 3, wn = wid >> 2;
    const int gm = lane >> 2, gk = lane & 3;
    const int m0 = blockIdx.x * 128;
    const int r  = blockIdx.y;
    const uint32_t sbase = (uint32_t)__cvta_generic_to_shared(smem);
    const size_t cbase = (size_t)r * kNC * kD;

    if (tid < kNC) cns[tid] = g_cnorm[r * kNC + tid];

    float acc[2][4][4];
#pragma unroll
    for (int mt = 0; mt < 2; mt++)
#pragma unroll
        for (int nt = 0; nt < 4; nt++)
#pragma unroll
            for (int q = 0; q < 4; q++) acc[mt][nt][q] = 0.f;

    auto copy_chunk = [&](int c, int buf) {
        const int koff = c * 32;
        const uint32_t tb = sbase + (uint32_t)buf * kABufB;
        // A (teacher rows): 1024 float4 per part, 4 per thread
#pragma unroll
        for (int q = 0; q < 4; q++) {
            const int idx = q * 256 + tid;
            const int row = idx >> 3, f4 = idx & 7;
            const uint32_t doff = (uint32_t)(row * kPitch + f4 * 4) * 4;
            const size_t gA = (size_t)(m0 + row) * kD + koff + f4 * 4;
            CP_ASYNC16(tb + 0 * kATileB + doff, g_Bhi + gA);
            CP_ASYNC16(tb + 1 * kATileB + doff, g_Blo + gA);
        }
        // B (centroids): 512 float4 per part, 2 per thread
#pragma unroll
        for (int q = 0; q < 2; q++) {
            const int idx = q * 256 + tid;
            const int row = idx >> 3, f4 = idx & 7;
            const uint32_t doff = (uint32_t)(row * kPitch + f4 * 4) * 4;
            const size_t gC = cbase + (size_t)row * kD + koff + f4 * 4;
            CP_ASYNC16(tb + 2 * kATileB + 0 * kBTileB + doff, g_Chi + gC);
            CP_ASYNC16(tb + 2 * kATileB + 1 * kBTileB + doff, g_Clo + gC);
        }
        CP_COMMIT();
    };

    copy_chunk(0, 0);
    copy_chunk(1, 1);

    for (int c = 0; c < kChunks; c++) {
        if (c < kChunks - 1) { CP_WAIT1(); } else { CP_WAIT0(); }
        __syncthreads();
        const int buf = c & 1;
        const float* Ah = reinterpret_cast<const float*>(smem + (size_t)buf * kABufB);
        const float* Al = reinterpret_cast<const float*>(smem + (size_t)buf * kABufB + kATileB);
        const float* Bh = reinterpret_cast<const float*>(smem + (size_t)buf * kABufB + 2 * kATileB);
        const float* Bl = reinterpret_cast<const float*>(smem + (size_t)buf * kABufB + 2 * kATileB + kBTileB);

#pragma unroll
        for (int kk = 0; kk < 4; kk++) {
            const int kb = kk * 8 + gk;
            uint32_t ah[2][4], al[2][4];
#pragma unroll
            for (int mt = 0; mt < 2; mt++) {
                const int r0 = wm * 32 + mt * 16 + gm;
                ah[mt][0] = __float_as_uint(Ah[r0 * kPitch + kb]);
                ah[mt][1] = __float_as_uint(Ah[(r0 + 8) * kPitch + kb]);
                ah[mt][2] = __float_as_uint(Ah[r0 * kPitch + kb + 4]);
                ah[mt][3] = __float_as_uint(Ah[(r0 + 8) * kPitch + kb + 4]);
                al[mt][0] = __float_as_uint(Al[r0 * kPitch + kb]);
                al[mt][1] = __float_as_uint(Al[(r0 + 8) * kPitch + kb]);
                al[mt][2] = __float_as_uint(Al[r0 * kPitch + kb + 4]);
                al[mt][3] = __float_as_uint(Al[(r0 + 8) * kPitch + kb + 4]);
            }
#pragma unroll
            for (int nt = 0; nt < 4; nt++) {
                const int rB = wn * 32 + nt * 8 + gm;
                uint32_t bh0 = __float_as_uint(Bh[rB * kPitch + kb]);
                uint32_t bh1 = __float_as_uint(Bh[rB * kPitch + kb + 4]);
                uint32_t bl0 = __float_as_uint(Bl[rB * kPitch + kb]);
                uint32_t bl1 = __float_as_uint(Bl[rB * kPitch + kb + 4]);
                MMA_TF32(acc[0][nt], ah[0], bh0, bh1);
                MMA_TF32(acc[1][nt], ah[1], bh0, bh1);
                MMA_TF32(acc[0][nt], ah[0], bl0, bl1);
                MMA_TF32(acc[1][nt], ah[1], bl0, bl1);
                MMA_TF32(acc[0][nt], al[0], bh0, bh1);
                MMA_TF32(acc[1][nt], al[1], bh0, bh1);
            }
        }
        __syncthreads();
        if (c + 2 < kChunks) copy_chunk(c + 2, (c + 2) & 1);
    }

    // argmin: per lane, rows (wm*32+mt*16+gm) and (+8); cols wn*32+nt*8+2gk+{0,1}
#pragma unroll
    for (int mt = 0; mt < 2; mt++) {
#pragma unroll
        for (int half = 0; half < 2; half++) {
            float bv = 3.402823466e38f;
            int   bi = 0x7fffffff;
#pragma unroll
            for (int nt = 0; nt < 4; nt++) {
                const int c0 = wn * 32 + nt * 8 + 2 * gk;
                float v0 = cns[c0]     - 2.f * acc[mt][nt][half * 2 + 0];
                float v1 = cns[c0 + 1] - 2.f * acc[mt][nt][half * 2 + 1];
                if (better(v0, c0, bv, bi))     { bv = v0; bi = c0; }
                if (better(v1, c0 + 1, bv, bi)) { bv = v1; bi = c0 + 1; }
            }
#pragma unroll
            for (int m = 1; m < 4; m <<= 1) {     // reduce over gk lanes
                float ov = __shfl_xor_sync(0xffffffffu, bv, m);
                int   oi = __shfl_xor_sync(0xffffffffu, bi, m);
                if (better(ov, oi, bv, bi)) { bv = ov; bi = oi; }
            }
            if (gk == 0) {
                const int rl = wm * 32 + mt * 16 + half * 8 + gm;
                sd[wn][rl] = bv;
                sidx[wn][rl] = bi;
            }
        }
    }
    __syncthreads();
    if (tid < 128) {
        float v0 = sd[0][tid]; int i0 = sidx[0][tid];
        float v1 = sd[1][tid]; int i1 = sidx[1][tid];
        g_labels[r * kN + m0 + tid] = better(v0, i0, v1, i1) ? i0 : i1;
    }
}

// ---------------- kernel 6a: point-centric partial sums (d-split) ----------------
__global__ void __launch_bounds__(256) partial_kernel(const float* __restrict__ X)
{
    extern __shared__ float sm[];
    float* ssum = sm;                            // [kNC][256]
    int*   slab = (int*)(sm + kNC * 256);        // [kCHP]
    int*   scnt = (int*)(sm + kNC * 256) + kCHP; // [kNC]

    const int ch = blockIdx.x;
    const int r  = blockIdx.y >> 1, dh = blockIdx.y & 1;
    const int t = threadIdx.x;
    const int d = dh * 256 + t;
    const int p0 = ch * kCHP;
    const int* lab = g_labels + r * kN;

#pragma unroll
    for (int c = 0; c < kNC; c++) ssum[c * 256 + t] = 0.f;
    if (t < kNC) scnt[t] = 0;
    slab[t] = lab[p0 + t];
    __syncthreads();
    if (dh == 0) atomicAdd(&scnt[slab[t]], 1);
    __syncthreads();

    for (int i = 0; i < kCHP; i += 8) {
        float x0 = X[(size_t)(p0 + i + 0) * kD + d];
        float x1 = X[(size_t)(p0 + i + 1) * kD + d];
        float x2 = X[(size_t)(p0 + i + 2) * kD + d];
        float x3 = X[(size_t)(p0 + i + 3) * kD + d];
        float x4 = X[(size_t)(p0 + i + 4) * kD + d];
        float x5 = X[(size_t)(p0 + i + 5) * kD + d];
        float x6 = X[(size_t)(p0 + i + 6) * kD + d];
        float x7 = X[(size_t)(p0 + i + 7) * kD + d];
        int c0 = slab[i + 0], c1 = slab[i + 1], c2 = slab[i + 2], c3 = slab[i + 3];
        int c4 = slab[i + 4], c5 = slab[i + 5], c6 = slab[i + 6], c7 = slab[i + 7];
        ssum[c0 * 256 + t] += x0;
        ssum[c1 * 256 + t] += x1;
        ssum[c2 * 256 + t] += x2;
        ssum[c3 * 256 + t] += x3;
        ssum[c4 * 256 + t] += x4;
        ssum[c5 * 256 + t] += x5;
        ssum[c6 * 256 + t] += x6;
        ssum[c7 * 256 + t] += x7;
    }
    __syncthreads();

    const size_t base = (size_t)(r * kCH + ch) * kNC;
#pragma unroll
    for (int c = 0; c < kNC; c++)
        g_part[(base + c) * kD + d] = ssum[c * 256 + t];
    if (dh == 0 && t < kNC) g_pcnt[base + t] = scnt[t];
}

// ---------------- kernel 6b: combine partials -> centroid + norm ----------------
__global__ void __launch_bounds__(512) combine_kernel()
{
    __shared__ float fred[16];
    const int c = blockIdx.x, r = blockIdx.y;
    const int t = threadIdx.x;
    const unsigned lane = t & 31;

    int cnt = 0;
    float sum = 0.f;
#pragma unroll
    for (int ch = 0; ch < kCH; ch++) {
        size_t base = (size_t)(r * kCH + ch) * kNC + c;
        cnt += g_pcnt[base];
        sum += g_part[base * kD + t];
    }
    const int rc = r * kNC + c;
    float oldc = g_cent[(size_t)rc * kD + t];
    float newc = (cnt > 0) ? (sum / (float)cnt) : oldc;
    g_cent[(size_t)rc * kD + t] = newc;

    float sq = newc * newc;
#pragma unroll
    for (int m = 16; m >= 1; m >>= 1) sq += __shfl_xor_sync(0xffffffffu, sq, m);
    if (lane == 0) fred[t >> 5] = sq;
    __syncthreads();
    if (t == 0) {
        float s = 0.f;
        for (int w = 0; w < 16; w++) s += fred[w];
        g_cnorm[rc] = s;
    }
}

// ---------------- kernel 7: scatter final output ----------------
__global__ void __launch_bounds__(256) scatter_kernel(
    const float* __restrict__ adj, float* __restrict__ out)
{
    int e = blockIdx.x * blockDim.x + threadIdx.x;
    int i = e >> 4;
    int j = g_knn[e];
    float v = adj[(size_t)i * kN + j];
    bool m = false;
#pragma unroll
    for (int r = 0; r < kNR; r++)
        m |= (g_labels[r * kN + i] == g_labels[r * kN + j]);
    out[(size_t)i * kN + j] = v + (m ? 1.f : 0.f);
}

// ---------------- launcher ----------------
extern "C" void kernel_launch(void* const* d_in, const int* in_sizes, int n_in,
                              void* d_out, int out_size)
{
    (void)in_sizes; (void)n_in; (void)out_size;
    const float* adj     = (const float*)d_in[0];
    const float* student = (const float*)d_in[1];
    const float* teacher = (const float*)d_in[2];
    float* out = (float*)d_out;

    constexpr size_t kPartSmem   = (size_t)kNC * 256 * 4 + kCHP * 4 + kNC * 4;
    constexpr size_t kGemmSmem   = 8 * (size_t)kTileB;      // 144 KB
    constexpr size_t kAssignSmem = 2 * (size_t)kABufB;      // 110.6 KB
    static cudaStream_t s2 = nullptr, s1 = nullptr;
    static cudaEvent_t ev_fork = nullptr, ev_join = nullptr, ev_main = nullptr, ev_split = nullptr;
    if (!s2) {
        int lo, hi;
        cudaDeviceGetStreamPriorityRange(&lo, &hi);
        cudaStreamCreateWithPriority(&s2, cudaStreamNonBlocking, hi);
        cudaStreamCreateWithPriority(&s1, cudaStreamNonBlocking, lo);
        cudaEventCreateWithFlags(&ev_fork, cudaEventDisableTiming);
        cudaEventCreateWithFlags(&ev_join, cudaEventDisableTiming);
        cudaEventCreateWithFlags(&ev_main, cudaEventDisableTiming);
        cudaEventCreateWithFlags(&ev_split, cudaEventDisableTiming);
        cudaFuncSetAttribute(partial_kernel,
                             cudaFuncAttributeMaxDynamicSharedMemorySize, (int)kPartSmem);
        cudaFuncSetAttribute(gemm_mma_kernel,
                             cudaFuncAttributeMaxDynamicSharedMemorySize, (int)kGemmSmem);
        cudaFuncSetAttribute(assign_mma_kernel,
                             cudaFuncAttributeMaxDynamicSharedMemorySize, (int)kAssignSmem);
    }

    IdxArr ia;
    compute_init_indices(ia.v);

    cudaEventRecord(ev_fork, 0);
    cudaStreamWaitEvent(s2, ev_fork, 0);
    cudaStreamWaitEvent(s1, ev_fork, 0);

    // s1 first: input tf32 split (teacher hi/lo also feeds assign on s2)
    split_kernel<<<(kN * kD) / (256 * 4), 256, 0, s1>>>(student, teacher);
    cudaEventRecord(ev_split, s1);

    // s2: serial kmeans chain (tensor-core assign)
    gather_kernel<<<kRC, 128, 0, s2>>>(teacher, ia);
    cnorm_kernel<<<kRC, 128, 0, s2>>>();
    split_cent_kernel<<<(kRC * kD) / (256 * 4), 256, 0, s2>>>();
    cudaStreamWaitEvent(s2, ev_split, 0);   // teacher hi/lo ready
    dim3 ga(kN / 128, kNR), gp(kCH, kNR * 2), gc(kNC, kNR);
    for (int it = 0; it < kIters; it++) {
        assign_mma_kernel<<<ga, 256, kAssignSmem, s2>>>();
        partial_kernel<<<gp, 256, kPartSmem, s2>>>(teacher);
        combine_kernel<<<gc, 512, 0, s2>>>();
        split_cent_kernel<<<(kRC * kD) / (256 * 4), 256, 0, s2>>>();
    }
    assign_mma_kernel<<<ga, 256, kAssignSmem, s2>>>();
    cudaEventRecord(ev_join, s2);

    // s1: tensor-core sim GEMM -> topk -> zero out
    dim3 g1(kN / 128, kN / 128);
    gemm_mma_kernel<<<g1, 256, kGemmSmem, s1>>>(out);
    topk_kernel<<<kN, 256, 0, s1>>>(out);
    cudaMemsetAsync(d_out, 0, (size_t)kN * kN * sizeof(float), s1);
    cudaEventRecord(ev_main, s1);

    cudaStreamWaitEvent(0, ev_join, 0);
    cudaStreamWaitEvent(0, ev_main, 0);
    scatter_kernel<<<kN * kTK / 256, 256>>>(adj, out);
}